// round 2
// baseline (speedup 1.0000x reference)
#include <cuda_runtime.h>
#include <math.h>

#define DIMC   256
#define HEADS  4
#define HEAD_DIM 64
#define KEY_DIM  32
#define HIDDEN 512
#define BATCH  2
#define NPIX   4096
#define HWDIM  64
#define EPSBN  1e-5f

// Scratch (allocation-free rule: __device__ globals)
__device__ float g_qkv[BATCH * HIDDEN * NPIX]; // 16 MB
__device__ float g_y  [BATCH * DIMC  * NPIX];  //  8 MB

// ---------------------------------------------------------------------------
// Tiled SGEMM + folded BatchNorm epilogue.
// Out[b][m][n] = BN( sum_k W[m][k] * X[b][k][n] )
// Tile: BM=64, BN=64, BK=16. 256 threads, 4x4 micro-tile per thread.
// ---------------------------------------------------------------------------
__global__ __launch_bounds__(256) void gemm_bn_kernel(
    const float* __restrict__ X, const float* __restrict__ W,
    const float* __restrict__ gg, const float* __restrict__ bb,
    const float* __restrict__ mm, const float* __restrict__ vv,
    float* __restrict__ Out, int M, int K)
{
    __shared__ float Ws[16][64];   // [k][m]
    __shared__ float Xs[16][64];   // [k][n]

    const int n0 = blockIdx.x * 64;
    const int m0 = blockIdx.y * 64;
    const int bz = blockIdx.z;
    const float* Xb = X + (size_t)bz * K * NPIX;
    float*       Ob = Out + (size_t)bz * M * NPIX;

    const int t  = threadIdx.x;
    const int tx = t & 15;        // n micro
    const int ty = t >> 4;        // m micro
    const int wr = t & 63;        // W-load row within tile
    const int wc = t >> 6;        // W-load float4 slot (0..3)

    float acc[4][4];
#pragma unroll
    for (int i = 0; i < 4; i++)
#pragma unroll
        for (int j = 0; j < 4; j++) acc[i][j] = 0.f;

    for (int k0 = 0; k0 < K; k0 += 16) {
        // W tile: each thread loads one float4 along k of one m-row.
        {
            float4 w4 = *(const float4*)&W[(size_t)(m0 + wr) * K + k0 + wc * 4];
            Ws[wc * 4 + 0][wr] = w4.x;
            Ws[wc * 4 + 1][wr] = w4.y;
            Ws[wc * 4 + 2][wr] = w4.z;
            Ws[wc * 4 + 3][wr] = w4.w;
        }
        // X tile: coalesced rows of 64.
#pragma unroll
        for (int i = 0; i < 4; i++) {
            int idx = t + i * 256;
            int kk = idx >> 6, nn = idx & 63;
            Xs[kk][nn] = Xb[(size_t)(k0 + kk) * NPIX + n0 + nn];
        }
        __syncthreads();
#pragma unroll
        for (int k = 0; k < 16; k++) {
            float4 a = *(const float4*)&Ws[k][ty * 4];
            float4 x4 = *(const float4*)&Xs[k][tx * 4];
            acc[0][0] += a.x * x4.x; acc[0][1] += a.x * x4.y; acc[0][2] += a.x * x4.z; acc[0][3] += a.x * x4.w;
            acc[1][0] += a.y * x4.x; acc[1][1] += a.y * x4.y; acc[1][2] += a.y * x4.z; acc[1][3] += a.y * x4.w;
            acc[2][0] += a.z * x4.x; acc[2][1] += a.z * x4.y; acc[2][2] += a.z * x4.z; acc[2][3] += a.z * x4.w;
            acc[3][0] += a.w * x4.x; acc[3][1] += a.w * x4.y; acc[3][2] += a.w * x4.z; acc[3][3] += a.w * x4.w;
        }
        __syncthreads();
    }

#pragma unroll
    for (int i = 0; i < 4; i++) {
        int row = m0 + ty * 4 + i;
        float sc = gg[row] * rsqrtf(vv[row] + EPSBN);
        float bi = bb[row] - mm[row] * sc;
        float4 o;
        o.x = acc[i][0] * sc + bi;
        o.y = acc[i][1] * sc + bi;
        o.z = acc[i][2] * sc + bi;
        o.w = acc[i][3] * sc + bi;
        *(float4*)&Ob[(size_t)row * NPIX + n0 + tx * 4] = o;
    }
}

// ---------------------------------------------------------------------------
// Flash attention. 1 thread = 1 query. Block = 128 queries.
// Grid = (NPIX/128, BATCH*HEADS).
// q scaled by (1/sqrt(32))*log2(e) so softmax runs in exp2 space.
// Scores computed in two halves of 16 to cap live registers.
// ---------------------------------------------------------------------------
__global__ __launch_bounds__(128) void attn_kernel()
{
    const int bh = blockIdx.y;
    const int b  = bh >> 2;
    const int h  = bh & 3;
    const float* base = g_qkv + ((size_t)b * HIDDEN + h * 128) * NPIX;
    const float* kbase = base + 32 * NPIX;
    const float* vbase = base + 64 * NPIX;

    const int t = threadIdx.x;
    const int i = blockIdx.x * 128 + t;

    __shared__ float k_s[32][32];   // [d][j]
    __shared__ float v_s[32][68];   // [j][dv] padded

    const float QSCALE = 0.17677669529663687f * 1.4426950408889634f;

    float q[32];
#pragma unroll
    for (int d = 0; d < 32; d++) q[d] = base[(size_t)d * NPIX + i] * QSCALE;

    float o[64];
#pragma unroll
    for (int dv = 0; dv < 64; dv++) o[dv] = 0.f;
    float mmax = -1e30f, l = 0.f;

    for (int kb = 0; kb < NPIX; kb += 32) {
        __syncthreads();
#pragma unroll
        for (int r = 0; r < 8; r++) {       // K tile: 1024 elems
            int idx = t + r * 128;
            int d = idx >> 5, j = idx & 31;
            k_s[d][j] = kbase[(size_t)d * NPIX + kb + j];
        }
#pragma unroll
        for (int r = 0; r < 16; r++) {      // V tile (transposed): 2048 elems
            int idx = t + r * 128;
            int dv = idx >> 5, j = idx & 31;
            v_s[j][dv] = vbase[(size_t)dv * NPIX + kb + j];
        }
        __syncthreads();

        // ---- scores + online softmax, two halves of 16 columns ----
        float p[32];
        float bm = -1e30f;
#pragma unroll
        for (int half = 0; half < 2; half++) {
            float s[16];
#pragma unroll
            for (int j = 0; j < 16; j++) s[j] = 0.f;
#pragma unroll
            for (int d = 0; d < 32; d++) {
                float qd = q[d];
                const float4* row = (const float4*)&k_s[d][half * 16];
#pragma unroll
                for (int jj = 0; jj < 4; jj++) {
                    float4 kk4 = row[jj];
                    s[jj * 4 + 0] += qd * kk4.x;
                    s[jj * 4 + 1] += qd * kk4.y;
                    s[jj * 4 + 2] += qd * kk4.z;
                    s[jj * 4 + 3] += qd * kk4.w;
                }
            }
#pragma unroll
            for (int j = 0; j < 16; j++) {
                p[half * 16 + j] = s[j];
                bm = fmaxf(bm, s[j]);
            }
        }
        bm = fmaxf(bm, mmax);
        float corr = exp2f(mmax - bm);
        mmax = bm;
        float psum = 0.f;
#pragma unroll
        for (int j = 0; j < 32; j++) { p[j] = exp2f(p[j] - bm); psum += p[j]; }
        l = l * corr + psum;
#pragma unroll
        for (int dv = 0; dv < 64; dv++) o[dv] *= corr;

#pragma unroll
        for (int j = 0; j < 32; j++) {
            float pj = p[j];
            const float4* vrow = (const float4*)&v_s[j][0];
#pragma unroll
            for (int dd = 0; dd < 16; dd++) {
                float4 vv4 = vrow[dd];
                o[dd * 4 + 0] += pj * vv4.x;
                o[dd * 4 + 1] += pj * vv4.y;
                o[dd * 4 + 2] += pj * vv4.z;
                o[dd * 4 + 3] += pj * vv4.w;
            }
        }
    }

    float inv = 1.f / l;
    float* ybase = g_y + ((size_t)b * DIMC + h * 64) * NPIX;
#pragma unroll
    for (int dv = 0; dv < 64; dv++)
        ybase[(size_t)dv * NPIX + i] = o[dv] * inv;
}

// ---------------------------------------------------------------------------
// Depthwise 3x3 conv (pad 1) on V image + BN, added into g_y.
// ---------------------------------------------------------------------------
__global__ __launch_bounds__(256) void pe_add_kernel(
    const float* __restrict__ pw, const float* __restrict__ pg,
    const float* __restrict__ pb, const float* __restrict__ pm,
    const float* __restrict__ pv)
{
    int idx = blockIdx.x * 256 + threadIdx.x;
    if (idx >= BATCH * DIMC * NPIX) return;
    int n = idx & 4095;
    int c = (idx >> 12) & 255;
    int b = idx >> 20;
    int yy = n >> 6, xx = n & 63;

    int vrow = (c >> 6) * 128 + 64 + (c & 63);
    const float* vimg = g_qkv + ((size_t)b * HIDDEN + vrow) * NPIX;

    float sum = 0.f;
#pragma unroll
    for (int ky = 0; ky < 3; ky++) {
        int y2 = yy + ky - 1;
        if (y2 < 0 || y2 >= HWDIM) continue;
#pragma unroll
        for (int kx = 0; kx < 3; kx++) {
            int x2 = xx + kx - 1;
            if (x2 < 0 || x2 >= HWDIM) continue;
            sum += pw[c * 9 + ky * 3 + kx] * vimg[y2 * HWDIM + x2];
        }
    }
    float sc = pg[c] * rsqrtf(pv[c] + EPSBN);
    g_y[idx] += sum * sc + (pb[c] - pm[c] * sc);
}

// ---------------------------------------------------------------------------
extern "C" void kernel_launch(void* const* d_in, const int* in_sizes, int n_in,
                              void* d_out, int out_size)
{
    const float* x      = (const float*)d_in[0];
    const float* qkv_w  = (const float*)d_in[1];
    const float* qkv_g  = (const float*)d_in[2];
    const float* qkv_b  = (const float*)d_in[3];
    const float* qkv_m  = (const float*)d_in[4];
    const float* qkv_v  = (const float*)d_in[5];
    const float* proj_w = (const float*)d_in[6];
    const float* proj_g = (const float*)d_in[7];
    const float* proj_b = (const float*)d_in[8];
    const float* proj_m = (const float*)d_in[9];
    const float* proj_v = (const float*)d_in[10];
    const float* pe_w   = (const float*)d_in[11];
    const float* pe_g   = (const float*)d_in[12];
    const float* pe_b   = (const float*)d_in[13];
    const float* pe_m   = (const float*)d_in[14];
    const float* pe_v   = (const float*)d_in[15];
    float* out = (float*)d_out;

    static float* qkv_buf = nullptr;
    static float* y_buf   = nullptr;
    if (!qkv_buf) {
        cudaGetSymbolAddress((void**)&qkv_buf, g_qkv);
        cudaGetSymbolAddress((void**)&y_buf,   g_y);
    }

    // 1) QKV 1x1 conv + BN : [512,256] x [256,4096] per batch
    {
        dim3 grid(NPIX / 64, HIDDEN / 64, BATCH);
        gemm_bn_kernel<<<grid, 256>>>(x, qkv_w, qkv_g, qkv_b, qkv_m, qkv_v,
                                      qkv_buf, HIDDEN, DIMC);
    }
    // 2) Attention
    {
        dim3 grid(NPIX / 128, BATCH * HEADS);
        attn_kernel<<<grid, 128>>>();
    }
    // 3) PE depthwise conv + BN, add into y
    {
        int total = BATCH * DIMC * NPIX;
        pe_add_kernel<<<(total + 255) / 256, 256>>>(pe_w, pe_g, pe_b, pe_m, pe_v);
    }
    // 4) proj 1x1 conv + BN : [256,256] x [256,4096] per batch -> out
    {
        dim3 grid(NPIX / 64, DIMC / 64, BATCH);
        gemm_bn_kernel<<<grid, 256>>>(y_buf, proj_w, proj_g, proj_b, proj_m, proj_v,
                                      out, DIMC, DIMC);
    }
}

// round 3
// speedup vs baseline: 1.0784x; 1.0784x over previous
#include <cuda_runtime.h>
#include <math.h>

#define DIMC   256
#define HEADS  4
#define HEAD_DIM 64
#define KEY_DIM  32
#define HIDDEN 512
#define BATCH  2
#define NPIX   4096
#define HWDIM  64
#define EPSBN  1e-5f

typedef unsigned long long u64;

// ---- packed fp32x2 helpers (SASS FFMA2 path, PTX-only) ----------------------
__device__ __forceinline__ u64 ffma2(u64 a, u64 b, u64 c) {
    u64 d; asm("fma.rn.f32x2 %0, %1, %2, %3;" : "=l"(d) : "l"(a), "l"(b), "l"(c));
    return d;
}
__device__ __forceinline__ u64 fmul2(u64 a, u64 b) {
    u64 d; asm("mul.rn.f32x2 %0, %1, %2;" : "=l"(d) : "l"(a), "l"(b));
    return d;
}
__device__ __forceinline__ u64 pack2(float lo, float hi) {
    u64 d; asm("mov.b64 %0, {%1, %2};" : "=l"(d) : "f"(lo), "f"(hi));
    return d;
}
__device__ __forceinline__ float2 unpack2(u64 v) {
    float2 f; asm("mov.b64 {%0, %1}, %2;" : "=f"(f.x), "=f"(f.y) : "l"(v));
    return f;
}
__device__ __forceinline__ float ex2(float x) {
    float y; asm("ex2.approx.ftz.f32 %0, %1;" : "=f"(y) : "f"(x));
    return y;
}

// Scratch (allocation-free rule: __device__ globals)
__device__ float g_qkv[BATCH * HIDDEN * NPIX]; // 16 MB
__device__ float g_y  [BATCH * DIMC  * NPIX];  //  8 MB

// ---------------------------------------------------------------------------
// Tiled SGEMM + folded BatchNorm epilogue, f32x2 inner product.
// Out[b][m][n] = BN( sum_k W[m][k] * X[b][k][n] )
// Tile: BM=64, BN=64, BK=16. 256 threads, 4x4 micro-tile per thread.
// ---------------------------------------------------------------------------
__global__ __launch_bounds__(256) void gemm_bn_kernel(
    const float* __restrict__ X, const float* __restrict__ W,
    const float* __restrict__ gg, const float* __restrict__ bb,
    const float* __restrict__ mm, const float* __restrict__ vv,
    float* __restrict__ Out, int M, int K)
{
    __shared__ float Ws[16][64];   // [k][m]
    __shared__ float Xs[16][64];   // [k][n]

    const int n0 = blockIdx.x * 64;
    const int m0 = blockIdx.y * 64;
    const int bz = blockIdx.z;
    const float* Xb = X + (size_t)bz * K * NPIX;
    float*       Ob = Out + (size_t)bz * M * NPIX;

    const int t  = threadIdx.x;
    const int tx = t & 15;        // n micro (float4 slot)
    const int ty = t >> 4;        // m micro
    const int wr = t & 63;        // W-load row within tile
    const int wc = t >> 6;        // W-load float4 slot (0..3)

    u64 acc2[4][2];
#pragma unroll
    for (int i = 0; i < 4; i++) { acc2[i][0] = pack2(0.f, 0.f); acc2[i][1] = pack2(0.f, 0.f); }

    for (int k0 = 0; k0 < K; k0 += 16) {
        {
            float4 w4 = *(const float4*)&W[(size_t)(m0 + wr) * K + k0 + wc * 4];
            Ws[wc * 4 + 0][wr] = w4.x;
            Ws[wc * 4 + 1][wr] = w4.y;
            Ws[wc * 4 + 2][wr] = w4.z;
            Ws[wc * 4 + 3][wr] = w4.w;
        }
#pragma unroll
        for (int i = 0; i < 4; i++) {
            int idx = t + i * 256;
            int kk = idx >> 6, nn = idx & 63;
            Xs[kk][nn] = Xb[(size_t)(k0 + kk) * NPIX + n0 + nn];
        }
        __syncthreads();
#pragma unroll
        for (int k = 0; k < 16; k++) {
            float4 a = *(const float4*)&Ws[k][ty * 4];
            ulonglong2 x2 = ((const ulonglong2*)&Xs[k][0])[tx];
            u64 a0 = pack2(a.x, a.x);
            u64 a1 = pack2(a.y, a.y);
            u64 a2 = pack2(a.z, a.z);
            u64 a3 = pack2(a.w, a.w);
            acc2[0][0] = ffma2(a0, x2.x, acc2[0][0]); acc2[0][1] = ffma2(a0, x2.y, acc2[0][1]);
            acc2[1][0] = ffma2(a1, x2.x, acc2[1][0]); acc2[1][1] = ffma2(a1, x2.y, acc2[1][1]);
            acc2[2][0] = ffma2(a2, x2.x, acc2[2][0]); acc2[2][1] = ffma2(a2, x2.y, acc2[2][1]);
            acc2[3][0] = ffma2(a3, x2.x, acc2[3][0]); acc2[3][1] = ffma2(a3, x2.y, acc2[3][1]);
        }
        __syncthreads();
    }

#pragma unroll
    for (int i = 0; i < 4; i++) {
        int row = m0 + ty * 4 + i;
        float sc = gg[row] * rsqrtf(vv[row] + EPSBN);
        float bi = bb[row] - mm[row] * sc;
        float2 p0 = unpack2(acc2[i][0]);
        float2 p1 = unpack2(acc2[i][1]);
        float4 o;
        o.x = p0.x * sc + bi;
        o.y = p0.y * sc + bi;
        o.z = p1.x * sc + bi;
        o.w = p1.y * sc + bi;
        *(float4*)&Ob[(size_t)row * NPIX + n0 + tx * 4] = o;
    }
}

// ---------------------------------------------------------------------------
// Flash attention, f32x2 math. 1 thread = 1 query. Block = 128 queries.
// Grid = (NPIX/128, BATCH*HEADS).
// q scaled by (1/sqrt(32))*log2(e) so softmax runs in exp2 space.
// ---------------------------------------------------------------------------
__global__ __launch_bounds__(128) void attn_kernel()
{
    const int bh = blockIdx.y;
    const int b  = bh >> 2;
    const int h  = bh & 3;
    const float* base  = g_qkv + ((size_t)b * HIDDEN + h * 128) * NPIX;
    const float* kbase = base + 32 * NPIX;
    const float* vbase = base + 64 * NPIX;

    const int t = threadIdx.x;
    const int i = blockIdx.x * 128 + t;

    __shared__ float k_s[32][32];   // [d][j]
    __shared__ float v_s[32][68];   // [j][dv], stride 68 floats (16B aligned)

    const float QSCALE = 0.17677669529663687f * 1.4426950408889634f;

    float q[32];
#pragma unroll
    for (int d = 0; d < 32; d++) q[d] = base[(size_t)d * NPIX + i] * QSCALE;

    u64 o2[32];
#pragma unroll
    for (int k = 0; k < 32; k++) o2[k] = pack2(0.f, 0.f);
    float mmax = -1e30f, l = 0.f;

    for (int kb = 0; kb < NPIX; kb += 32) {
        __syncthreads();
#pragma unroll
        for (int r = 0; r < 8; r++) {       // K tile: 1024 elems
            int idx = t + r * 128;
            int d = idx >> 5, j = idx & 31;
            k_s[d][j] = kbase[(size_t)d * NPIX + kb + j];
        }
#pragma unroll
        for (int r = 0; r < 16; r++) {      // V tile (transposed): 2048 elems
            int idx = t + r * 128;
            int dv = idx >> 5, j = idx & 31;
            v_s[j][dv] = vbase[(size_t)dv * NPIX + kb + j];
        }
        __syncthreads();

        // ---- scores: 16 packed pairs over 32 keys ----
        u64 s2[16];
#pragma unroll
        for (int jj = 0; jj < 16; jj++) s2[jj] = pack2(0.f, 0.f);
#pragma unroll
        for (int d = 0; d < 32; d++) {
            u64 qq = pack2(q[d], q[d]);
            const ulonglong2* row = (const ulonglong2*)&k_s[d][0];
#pragma unroll
            for (int jj = 0; jj < 8; jj++) {
                ulonglong2 kk = row[jj];
                s2[jj * 2 + 0] = ffma2(qq, kk.x, s2[jj * 2 + 0]);
                s2[jj * 2 + 1] = ffma2(qq, kk.y, s2[jj * 2 + 1]);
            }
        }

        // ---- online softmax ----
        float p[32];
        float bm = mmax;
#pragma unroll
        for (int jj = 0; jj < 16; jj++) {
            float2 f = unpack2(s2[jj]);
            p[jj * 2 + 0] = f.x;
            p[jj * 2 + 1] = f.y;
            bm = fmaxf(bm, fmaxf(f.x, f.y));
        }
        float corr = ex2(mmax - bm);
        mmax = bm;
        float psum = 0.f;
#pragma unroll
        for (int j = 0; j < 32; j++) { p[j] = ex2(p[j] - bm); psum += p[j]; }
        l = l * corr + psum;
        u64 cc = pack2(corr, corr);
#pragma unroll
        for (int k = 0; k < 32; k++) o2[k] = fmul2(o2[k], cc);

        // ---- P * V : 32 packed pairs over dv ----
#pragma unroll
        for (int j = 0; j < 32; j++) {
            u64 pj = pack2(p[j], p[j]);
            const ulonglong2* vrow = (const ulonglong2*)&v_s[j][0];
#pragma unroll
            for (int dd = 0; dd < 16; dd++) {
                ulonglong2 vv4 = vrow[dd];
                o2[dd * 2 + 0] = ffma2(pj, vv4.x, o2[dd * 2 + 0]);
                o2[dd * 2 + 1] = ffma2(pj, vv4.y, o2[dd * 2 + 1]);
            }
        }
    }

    float inv = 1.f / l;
    float* ybase = g_y + ((size_t)b * DIMC + h * 64) * NPIX;
#pragma unroll
    for (int k = 0; k < 32; k++) {
        float2 f = unpack2(o2[k]);
        ybase[(size_t)(2 * k + 0) * NPIX + i] = f.x * inv;
        ybase[(size_t)(2 * k + 1) * NPIX + i] = f.y * inv;
    }
}

// ---------------------------------------------------------------------------
// Depthwise 3x3 conv (pad 1) on V image + BN, added into g_y.
// ---------------------------------------------------------------------------
__global__ __launch_bounds__(256) void pe_add_kernel(
    const float* __restrict__ pw, const float* __restrict__ pg,
    const float* __restrict__ pb, const float* __restrict__ pm,
    const float* __restrict__ pv)
{
    int idx = blockIdx.x * 256 + threadIdx.x;
    if (idx >= BATCH * DIMC * NPIX) return;
    int n = idx & 4095;
    int c = (idx >> 12) & 255;
    int b = idx >> 20;
    int yy = n >> 6, xx = n & 63;

    int vrow = (c >> 6) * 128 + 64 + (c & 63);
    const float* vimg = g_qkv + ((size_t)b * HIDDEN + vrow) * NPIX;

    float sum = 0.f;
#pragma unroll
    for (int ky = 0; ky < 3; ky++) {
        int y2 = yy + ky - 1;
        if (y2 < 0 || y2 >= HWDIM) continue;
#pragma unroll
        for (int kx = 0; kx < 3; kx++) {
            int x2 = xx + kx - 1;
            if (x2 < 0 || x2 >= HWDIM) continue;
            sum += pw[c * 9 + ky * 3 + kx] * vimg[y2 * HWDIM + x2];
        }
    }
    float sc = pg[c] * rsqrtf(pv[c] + EPSBN);
    g_y[idx] += sum * sc + (pb[c] - pm[c] * sc);
}

// ---------------------------------------------------------------------------
extern "C" void kernel_launch(void* const* d_in, const int* in_sizes, int n_in,
                              void* d_out, int out_size)
{
    const float* x      = (const float*)d_in[0];
    const float* qkv_w  = (const float*)d_in[1];
    const float* qkv_g  = (const float*)d_in[2];
    const float* qkv_b  = (const float*)d_in[3];
    const float* qkv_m  = (const float*)d_in[4];
    const float* qkv_v  = (const float*)d_in[5];
    const float* proj_w = (const float*)d_in[6];
    const float* proj_g = (const float*)d_in[7];
    const float* proj_b = (const float*)d_in[8];
    const float* proj_m = (const float*)d_in[9];
    const float* proj_v = (const float*)d_in[10];
    const float* pe_w   = (const float*)d_in[11];
    const float* pe_g   = (const float*)d_in[12];
    const float* pe_b   = (const float*)d_in[13];
    const float* pe_m   = (const float*)d_in[14];
    const float* pe_v   = (const float*)d_in[15];
    float* out = (float*)d_out;

    static float* qkv_buf = nullptr;
    static float* y_buf   = nullptr;
    if (!qkv_buf) {
        cudaGetSymbolAddress((void**)&qkv_buf, g_qkv);
        cudaGetSymbolAddress((void**)&y_buf,   g_y);
    }

    // 1) QKV 1x1 conv + BN : [512,256] x [256,4096] per batch
    {
        dim3 grid(NPIX / 64, HIDDEN / 64, BATCH);
        gemm_bn_kernel<<<grid, 256>>>(x, qkv_w, qkv_g, qkv_b, qkv_m, qkv_v,
                                      qkv_buf, HIDDEN, DIMC);
    }
    // 2) Attention
    {
        dim3 grid(NPIX / 128, BATCH * HEADS);
        attn_kernel<<<grid, 128>>>();
    }
    // 3) PE depthwise conv + BN, add into y
    {
        int total = BATCH * DIMC * NPIX;
        pe_add_kernel<<<(total + 255) / 256, 256>>>(pe_w, pe_g, pe_b, pe_m, pe_v);
    }
    // 4) proj 1x1 conv + BN : [256,256] x [256,4096] per batch -> out
    {
        dim3 grid(NPIX / 64, DIMC / 64, BATCH);
        gemm_bn_kernel<<<grid, 256>>>(y_buf, proj_w, proj_g, proj_b, proj_m, proj_v,
                                      out, DIMC, DIMC);
    }
}

// round 4
// speedup vs baseline: 2.8284x; 2.6228x over previous
#include <cuda_runtime.h>
#include <math.h>

#define DIMC   256
#define HEADS  4
#define HEAD_DIM 64
#define KEY_DIM  32
#define HIDDEN 512
#define BATCH  2
#define NPIX   4096
#define HWDIM  64
#define EPSBN  1e-5f

typedef unsigned long long u64;
typedef unsigned int u32;

// ---- packed fp32x2 helpers (kept for GEMM; issue-slot relief) ---------------
__device__ __forceinline__ u64 ffma2(u64 a, u64 b, u64 c) {
    u64 d; asm("fma.rn.f32x2 %0, %1, %2, %3;" : "=l"(d) : "l"(a), "l"(b), "l"(c));
    return d;
}
__device__ __forceinline__ u64 pack2(float lo, float hi) {
    u64 d; asm("mov.b64 %0, {%1, %2};" : "=l"(d) : "f"(lo), "f"(hi));
    return d;
}
__device__ __forceinline__ float2 unpack2(u64 v) {
    float2 f; asm("mov.b64 {%0, %1}, %2;" : "=f"(f.x), "=f"(f.y) : "l"(v));
    return f;
}
__device__ __forceinline__ float ex2(float x) {
    float y; asm("ex2.approx.ftz.f32 %0, %1;" : "=f"(y) : "f"(x));
    return y;
}
__device__ __forceinline__ u32 cvt_tf32(float x) {
    u32 u; asm("cvt.rna.tf32.f32 %0, %1;" : "=r"(u) : "f"(x));
    return u;
}
// D += A(tf32 m16k8) * B(tf32 k8n8)
__device__ __forceinline__ void mma_tf32(float c[4], const u32 a[4], const u32 b[2]) {
    asm("mma.sync.aligned.m16n8k8.row.col.f32.tf32.tf32.f32 "
        "{%0,%1,%2,%3},{%4,%5,%6,%7},{%8,%9},{%0,%1,%2,%3};"
        : "+f"(c[0]), "+f"(c[1]), "+f"(c[2]), "+f"(c[3])
        : "r"(a[0]), "r"(a[1]), "r"(a[2]), "r"(a[3]), "r"(b[0]), "r"(b[1]));
}

// Scratch (allocation-free rule: __device__ globals)
__device__ float g_qkv[BATCH * HIDDEN * NPIX]; // 16 MB
__device__ float g_y  [BATCH * DIMC  * NPIX];  //  8 MB

// ---------------------------------------------------------------------------
// Tiled SGEMM + folded BatchNorm epilogue (unchanged from round 3).
// ---------------------------------------------------------------------------
__global__ __launch_bounds__(256) void gemm_bn_kernel(
    const float* __restrict__ X, const float* __restrict__ W,
    const float* __restrict__ gg, const float* __restrict__ bb,
    const float* __restrict__ mm, const float* __restrict__ vv,
    float* __restrict__ Out, int M, int K)
{
    __shared__ float Ws[16][64];
    __shared__ float Xs[16][64];

    const int n0 = blockIdx.x * 64;
    const int m0 = blockIdx.y * 64;
    const int bz = blockIdx.z;
    const float* Xb = X + (size_t)bz * K * NPIX;
    float*       Ob = Out + (size_t)bz * M * NPIX;

    const int t  = threadIdx.x;
    const int tx = t & 15;
    const int ty = t >> 4;
    const int wr = t & 63;
    const int wc = t >> 6;

    u64 acc2[4][2];
#pragma unroll
    for (int i = 0; i < 4; i++) { acc2[i][0] = pack2(0.f, 0.f); acc2[i][1] = pack2(0.f, 0.f); }

    for (int k0 = 0; k0 < K; k0 += 16) {
        {
            float4 w4 = *(const float4*)&W[(size_t)(m0 + wr) * K + k0 + wc * 4];
            Ws[wc * 4 + 0][wr] = w4.x;
            Ws[wc * 4 + 1][wr] = w4.y;
            Ws[wc * 4 + 2][wr] = w4.z;
            Ws[wc * 4 + 3][wr] = w4.w;
        }
#pragma unroll
        for (int i = 0; i < 4; i++) {
            int idx = t + i * 256;
            int kk = idx >> 6, nn = idx & 63;
            Xs[kk][nn] = Xb[(size_t)(k0 + kk) * NPIX + n0 + nn];
        }
        __syncthreads();
#pragma unroll
        for (int k = 0; k < 16; k++) {
            float4 a = *(const float4*)&Ws[k][ty * 4];
            ulonglong2 x2 = ((const ulonglong2*)&Xs[k][0])[tx];
            u64 a0 = pack2(a.x, a.x);
            u64 a1 = pack2(a.y, a.y);
            u64 a2 = pack2(a.z, a.z);
            u64 a3 = pack2(a.w, a.w);
            acc2[0][0] = ffma2(a0, x2.x, acc2[0][0]); acc2[0][1] = ffma2(a0, x2.y, acc2[0][1]);
            acc2[1][0] = ffma2(a1, x2.x, acc2[1][0]); acc2[1][1] = ffma2(a1, x2.y, acc2[1][1]);
            acc2[2][0] = ffma2(a2, x2.x, acc2[2][0]); acc2[2][1] = ffma2(a2, x2.y, acc2[2][1]);
            acc2[3][0] = ffma2(a3, x2.x, acc2[3][0]); acc2[3][1] = ffma2(a3, x2.y, acc2[3][1]);
        }
        __syncthreads();
    }

#pragma unroll
    for (int i = 0; i < 4; i++) {
        int row = m0 + ty * 4 + i;
        float sc = gg[row] * rsqrtf(vv[row] + EPSBN);
        float bi = bb[row] - mm[row] * sc;
        float2 p0 = unpack2(acc2[i][0]);
        float2 p1 = unpack2(acc2[i][1]);
        float4 o;
        o.x = p0.x * sc + bi;
        o.y = p0.y * sc + bi;
        o.z = p1.x * sc + bi;
        o.w = p1.y * sc + bi;
        *(float4*)&Ob[(size_t)row * NPIX + n0 + tx * 4] = o;
    }
}

// ---------------------------------------------------------------------------
// Flash attention via mma.sync tf32. Block = 128 threads (4 warps) = 64 queries.
// Warp w owns query rows [16w, 16w+16). KV tiles of 64 keys.
// Grid = (NPIX/64, BATCH*HEADS).
// ---------------------------------------------------------------------------
__global__ __launch_bounds__(128) void attn_mma_kernel()
{
    const int bh = blockIdx.y;
    const int b  = bh >> 2;
    const int h  = bh & 3;
    const float* base  = g_qkv + ((size_t)b * HIDDEN + h * 128) * NPIX;
    const float* kbase = base + 32 * NPIX;
    const float* vbase = base + 64 * NPIX;

    const int i0   = blockIdx.x * 64;
    const int t    = threadIdx.x;
    const int w    = t >> 5;
    const int lane = t & 31;
    const int r    = lane >> 2;   // 0..7
    const int cq   = lane & 3;    // 0..3

    // Strides chosen for conflict-free fragment LDS:
    //  Ks stride 72 (72%32==8): b-frag addr = 8*cq + r  -> 32 distinct banks
    //  Vs/Ps stride 68 (68%32==4): addr = 4*row + col   -> 32 distinct banks
    __shared__ u32 Ks[32][72];   // Ks[d][j]  (tf32)
    __shared__ u32 Vs[64][68];   // Vs[dv][j] (tf32)
    __shared__ u32 Ps[64][68];   // Ps[i][j]  (tf32) — warp-private row bands

    const float QSCALE = 0.17677669529663687f * 1.4426950408889634f;

    // Q fragments (row i0+16w+r / +8, k = ks*8 + cq / +4), loaded once.
    u32 qa[4][4];
#pragma unroll
    for (int ks = 0; ks < 4; ks++) {
        int d0 = ks * 8;
        qa[ks][0] = cvt_tf32(base[(size_t)(d0 + cq)     * NPIX + i0 + 16*w + r    ] * QSCALE);
        qa[ks][1] = cvt_tf32(base[(size_t)(d0 + cq)     * NPIX + i0 + 16*w + r + 8] * QSCALE);
        qa[ks][2] = cvt_tf32(base[(size_t)(d0 + cq + 4) * NPIX + i0 + 16*w + r    ] * QSCALE);
        qa[ks][3] = cvt_tf32(base[(size_t)(d0 + cq + 4) * NPIX + i0 + 16*w + r + 8] * QSCALE);
    }

    float o[8][4];
#pragma unroll
    for (int nt = 0; nt < 8; nt++)
#pragma unroll
        for (int k = 0; k < 4; k++) o[nt][k] = 0.f;

    float m0 = -1e30f, m1 = -1e30f, l0 = 0.f, l1 = 0.f;

    for (int kb = 0; kb < NPIX; kb += 64) {
        __syncthreads();
        // Stage K tile: 32 d x 64 j, float4 granules (512 total / 128 thr = 4 each)
#pragma unroll
        for (int c = 0; c < 4; c++) {
            int idx = t + c * 128;
            int d = idx >> 4, j4 = (idx & 15) * 4;
            float4 kv = *(const float4*)&kbase[(size_t)d * NPIX + kb + j4];
            uint4 kc;
            kc.x = cvt_tf32(kv.x); kc.y = cvt_tf32(kv.y);
            kc.z = cvt_tf32(kv.z); kc.w = cvt_tf32(kv.w);
            *(uint4*)&Ks[d][j4] = kc;
        }
        // Stage V tile: 64 dv x 64 j (1024 granules / 128 thr = 8 each)
#pragma unroll
        for (int c = 0; c < 8; c++) {
            int idx = t + c * 128;
            int dv = idx >> 4, j4 = (idx & 15) * 4;
            float4 vv = *(const float4*)&vbase[(size_t)dv * NPIX + kb + j4];
            uint4 vc;
            vc.x = cvt_tf32(vv.x); vc.y = cvt_tf32(vv.y);
            vc.z = cvt_tf32(vv.z); vc.w = cvt_tf32(vv.w);
            *(uint4*)&Vs[dv][j4] = vc;
        }
        __syncthreads();

        // ---- S = Q * K^T  (16 x 64 per warp) ----
        float s[8][4];
#pragma unroll
        for (int nt = 0; nt < 8; nt++)
#pragma unroll
            for (int k = 0; k < 4; k++) s[nt][k] = 0.f;
#pragma unroll
        for (int ks = 0; ks < 4; ks++) {
#pragma unroll
            for (int nt = 0; nt < 8; nt++) {
                u32 bf[2];
                bf[0] = Ks[ks * 8 + cq    ][nt * 8 + r];
                bf[1] = Ks[ks * 8 + cq + 4][nt * 8 + r];
                mma_tf32(s[nt], qa[ks], bf);
            }
        }

        // ---- online softmax on C fragments ----
        float mx0 = m0, mx1 = m1;
#pragma unroll
        for (int nt = 0; nt < 8; nt++) {
            mx0 = fmaxf(mx0, fmaxf(s[nt][0], s[nt][1]));
            mx1 = fmaxf(mx1, fmaxf(s[nt][2], s[nt][3]));
        }
        mx0 = fmaxf(mx0, __shfl_xor_sync(0xffffffffu, mx0, 1));
        mx0 = fmaxf(mx0, __shfl_xor_sync(0xffffffffu, mx0, 2));
        mx1 = fmaxf(mx1, __shfl_xor_sync(0xffffffffu, mx1, 1));
        mx1 = fmaxf(mx1, __shfl_xor_sync(0xffffffffu, mx1, 2));
        float corr0 = ex2(m0 - mx0);
        float corr1 = ex2(m1 - mx1);
        m0 = mx0; m1 = mx1;

        float ps0 = 0.f, ps1 = 0.f;
#pragma unroll
        for (int nt = 0; nt < 8; nt++) {
            s[nt][0] = ex2(s[nt][0] - m0);
            s[nt][1] = ex2(s[nt][1] - m0);
            s[nt][2] = ex2(s[nt][2] - m1);
            s[nt][3] = ex2(s[nt][3] - m1);
            ps0 += s[nt][0] + s[nt][1];
            ps1 += s[nt][2] + s[nt][3];
        }
        ps0 += __shfl_xor_sync(0xffffffffu, ps0, 1);
        ps0 += __shfl_xor_sync(0xffffffffu, ps0, 2);
        ps1 += __shfl_xor_sync(0xffffffffu, ps1, 1);
        ps1 += __shfl_xor_sync(0xffffffffu, ps1, 2);
        l0 = l0 * corr0 + ps0;
        l1 = l1 * corr1 + ps1;

#pragma unroll
        for (int nt = 0; nt < 8; nt++) {
            o[nt][0] *= corr0; o[nt][1] *= corr0;
            o[nt][2] *= corr1; o[nt][3] *= corr1;
        }

        // ---- write P fragments (warp-private rows) ----
#pragma unroll
        for (int nt = 0; nt < 8; nt++) {
            Ps[16*w + r    ][nt * 8 + 2*cq    ] = cvt_tf32(s[nt][0]);
            Ps[16*w + r    ][nt * 8 + 2*cq + 1] = cvt_tf32(s[nt][1]);
            Ps[16*w + r + 8][nt * 8 + 2*cq    ] = cvt_tf32(s[nt][2]);
            Ps[16*w + r + 8][nt * 8 + 2*cq + 1] = cvt_tf32(s[nt][3]);
        }
        __syncwarp();

        // ---- O += P * V  (K-dim = 64 keys) ----
#pragma unroll
        for (int ks2 = 0; ks2 < 8; ks2++) {
            u32 pa[4];
            pa[0] = Ps[16*w + r    ][ks2 * 8 + cq    ];
            pa[1] = Ps[16*w + r + 8][ks2 * 8 + cq    ];
            pa[2] = Ps[16*w + r    ][ks2 * 8 + cq + 4];
            pa[3] = Ps[16*w + r + 8][ks2 * 8 + cq + 4];
#pragma unroll
            for (int nt = 0; nt < 8; nt++) {
                u32 bf[2];
                bf[0] = Vs[nt * 8 + r][ks2 * 8 + cq    ];
                bf[1] = Vs[nt * 8 + r][ks2 * 8 + cq + 4];
                mma_tf32(o[nt], pa, bf);
            }
        }
        __syncwarp();
    }

    // ---- epilogue: normalize and store (g_y layout [dv][n]) ----
    float inv0 = 1.f / l0;
    float inv1 = 1.f / l1;
    float* ybase = g_y + ((size_t)b * DIMC + h * 64) * NPIX;
    int row0 = i0 + 16*w + r;
    int row1 = row0 + 8;
#pragma unroll
    for (int nt = 0; nt < 8; nt++) {
        int dv0 = nt * 8 + 2*cq;
        ybase[(size_t)(dv0    ) * NPIX + row0] = o[nt][0] * inv0;
        ybase[(size_t)(dv0 + 1) * NPIX + row0] = o[nt][1] * inv0;
        ybase[(size_t)(dv0    ) * NPIX + row1] = o[nt][2] * inv1;
        ybase[(size_t)(dv0 + 1) * NPIX + row1] = o[nt][3] * inv1;
    }
}

// ---------------------------------------------------------------------------
// Depthwise 3x3 conv (pad 1) on V image + BN, added into g_y.
// ---------------------------------------------------------------------------
__global__ __launch_bounds__(256) void pe_add_kernel(
    const float* __restrict__ pw, const float* __restrict__ pg,
    const float* __restrict__ pb, const float* __restrict__ pm,
    const float* __restrict__ pv)
{
    int idx = blockIdx.x * 256 + threadIdx.x;
    if (idx >= BATCH * DIMC * NPIX) return;
    int n = idx & 4095;
    int c = (idx >> 12) & 255;
    int b = idx >> 20;
    int yy = n >> 6, xx = n & 63;

    int vrow = (c >> 6) * 128 + 64 + (c & 63);
    const float* vimg = g_qkv + ((size_t)b * HIDDEN + vrow) * NPIX;

    float sum = 0.f;
#pragma unroll
    for (int ky = 0; ky < 3; ky++) {
        int y2 = yy + ky - 1;
        if (y2 < 0 || y2 >= HWDIM) continue;
#pragma unroll
        for (int kx = 0; kx < 3; kx++) {
            int x2 = xx + kx - 1;
            if (x2 < 0 || x2 >= HWDIM) continue;
            sum += pw[c * 9 + ky * 3 + kx] * vimg[y2 * HWDIM + x2];
        }
    }
    float sc = pg[c] * rsqrtf(pv[c] + EPSBN);
    g_y[idx] += sum * sc + (pb[c] - pm[c] * sc);
}

// ---------------------------------------------------------------------------
extern "C" void kernel_launch(void* const* d_in, const int* in_sizes, int n_in,
                              void* d_out, int out_size)
{
    const float* x      = (const float*)d_in[0];
    const float* qkv_w  = (const float*)d_in[1];
    const float* qkv_g  = (const float*)d_in[2];
    const float* qkv_b  = (const float*)d_in[3];
    const float* qkv_m  = (const float*)d_in[4];
    const float* qkv_v  = (const float*)d_in[5];
    const float* proj_w = (const float*)d_in[6];
    const float* proj_g = (const float*)d_in[7];
    const float* proj_b = (const float*)d_in[8];
    const float* proj_m = (const float*)d_in[9];
    const float* proj_v = (const float*)d_in[10];
    const float* pe_w   = (const float*)d_in[11];
    const float* pe_g   = (const float*)d_in[12];
    const float* pe_b   = (const float*)d_in[13];
    const float* pe_m   = (const float*)d_in[14];
    const float* pe_v   = (const float*)d_in[15];
    float* out = (float*)d_out;

    static float* qkv_buf = nullptr;
    static float* y_buf   = nullptr;
    if (!qkv_buf) {
        cudaGetSymbolAddress((void**)&qkv_buf, g_qkv);
        cudaGetSymbolAddress((void**)&y_buf,   g_y);
    }

    // 1) QKV 1x1 conv + BN : [512,256] x [256,4096] per batch
    {
        dim3 grid(NPIX / 64, HIDDEN / 64, BATCH);
        gemm_bn_kernel<<<grid, 256>>>(x, qkv_w, qkv_g, qkv_b, qkv_m, qkv_v,
                                      qkv_buf, HIDDEN, DIMC);
    }
    // 2) Attention (tensor-core tf32)
    {
        dim3 grid(NPIX / 64, BATCH * HEADS);
        attn_mma_kernel<<<grid, 128>>>();
    }
    // 3) PE depthwise conv + BN, add into y
    {
        int total = BATCH * DIMC * NPIX;
        pe_add_kernel<<<(total + 255) / 256, 256>>>(pe_w, pe_g, pe_b, pe_m, pe_v);
    }
    // 4) proj 1x1 conv + BN : [256,256] x [256,4096] per batch -> out
    {
        dim3 grid(NPIX / 64, DIMC / 64, BATCH);
        gemm_bn_kernel<<<grid, 256>>>(y_buf, proj_w, proj_g, proj_b, proj_m, proj_v,
                                      out, DIMC, DIMC);
    }
}

// round 5
// speedup vs baseline: 3.5702x; 1.2623x over previous
#include <cuda_runtime.h>
#include <math.h>

#define DIMC   256
#define HEADS  4
#define HEAD_DIM 64
#define KEY_DIM  32
#define HIDDEN 512
#define BATCH  2
#define NPIX   4096
#define HWDIM  64
#define EPSBN  1e-5f

typedef unsigned long long u64;
typedef unsigned int u32;

__device__ __forceinline__ float ex2(float x) {
    float y; asm("ex2.approx.ftz.f32 %0, %1;" : "=f"(y) : "f"(x));
    return y;
}
__device__ __forceinline__ u32 cvt_tf32(float x) {
    u32 u; asm("cvt.rna.tf32.f32 %0, %1;" : "=r"(u) : "f"(x));
    return u;
}
// D += A(tf32 m16k8) * B(tf32 k8n8)
__device__ __forceinline__ void mma_tf32(float c[4], const u32 a[4], const u32 b[2]) {
    asm("mma.sync.aligned.m16n8k8.row.col.f32.tf32.tf32.f32 "
        "{%0,%1,%2,%3},{%4,%5,%6,%7},{%8,%9},{%0,%1,%2,%3};"
        : "+f"(c[0]), "+f"(c[1]), "+f"(c[2]), "+f"(c[3])
        : "r"(a[0]), "r"(a[1]), "r"(a[2]), "r"(a[3]), "r"(b[0]), "r"(b[1]));
}
__device__ __forceinline__ void cp16(u32 dst, const void* src) {
    asm volatile("cp.async.ca.shared.global [%0], [%1], 16;" :: "r"(dst), "l"(src));
}
__device__ __forceinline__ void cp_commit() {
    asm volatile("cp.async.commit_group;" ::: "memory");
}
__device__ __forceinline__ void cp_wait0() {
    asm volatile("cp.async.wait_group 0;" ::: "memory");
}

// Scratch (allocation-free rule: __device__ globals)
__device__ float g_qkv[BATCH * HIDDEN * NPIX]; // 16 MB
__device__ float g_y  [BATCH * DIMC  * NPIX];  //  8 MB

// ---------------------------------------------------------------------------
// tf32 tensor-core GEMM + folded BN epilogue.
// Out[b][m][n] = BN( sum_k W[m][k] * X[b][k][n] ),  tile 64x64, K-chunk 32.
// 128 threads (4 warps); warp w owns m-rows [16w,16w+16), 8 n-tiles of 8.
// ---------------------------------------------------------------------------
__global__ __launch_bounds__(128) void gemm_mma_kernel(
    const float* __restrict__ X, const float* __restrict__ W,
    const float* __restrict__ gg, const float* __restrict__ bb,
    const float* __restrict__ mm, const float* __restrict__ vv,
    float* __restrict__ Out, int M, int K)
{
    __shared__ u32 Wsm[32][72];   // [k][m]  bank: (8k + m)%32 conflict-free
    __shared__ u32 Xsm[32][72];   // [k][n]

    const int n0 = blockIdx.x * 64;
    const int m0 = blockIdx.y * 64;
    const int bz = blockIdx.z;
    const float* Xb = X + (size_t)bz * K * NPIX;
    float*       Ob = Out + (size_t)bz * M * NPIX;

    const int t    = threadIdx.x;
    const int w    = t >> 5;
    const int lane = t & 31;
    const int r    = lane >> 2;
    const int cq   = lane & 3;

    float acc[8][4];
#pragma unroll
    for (int nt = 0; nt < 8; nt++)
#pragma unroll
        for (int k = 0; k < 4; k++) acc[nt][k] = 0.f;

    for (int k0 = 0; k0 < K; k0 += 32) {
#pragma unroll
        for (int i = 0; i < 4; i++) {           // W tile 64m x 32k
            int idx = t + i * 128;
            int m = idx & 63, kc = idx >> 6;    // kc 0..7
            float4 w4 = *(const float4*)&W[(size_t)(m0 + m) * K + k0 + kc * 4];
            Wsm[kc * 4 + 0][m] = cvt_tf32(w4.x);
            Wsm[kc * 4 + 1][m] = cvt_tf32(w4.y);
            Wsm[kc * 4 + 2][m] = cvt_tf32(w4.z);
            Wsm[kc * 4 + 3][m] = cvt_tf32(w4.w);
        }
#pragma unroll
        for (int i = 0; i < 4; i++) {           // X tile 32k x 64n
            int idx = t + i * 128;
            int kk = idx >> 4, n4 = (idx & 15) * 4;
            float4 x4 = *(const float4*)&Xb[(size_t)(k0 + kk) * NPIX + n0 + n4];
            Xsm[kk][n4 + 0] = cvt_tf32(x4.x);
            Xsm[kk][n4 + 1] = cvt_tf32(x4.y);
            Xsm[kk][n4 + 2] = cvt_tf32(x4.z);
            Xsm[kk][n4 + 3] = cvt_tf32(x4.w);
        }
        __syncthreads();
#pragma unroll
        for (int ks = 0; ks < 4; ks++) {
            u32 a[4];
            a[0] = Wsm[ks * 8 + cq    ][16 * w + r    ];
            a[1] = Wsm[ks * 8 + cq    ][16 * w + r + 8];
            a[2] = Wsm[ks * 8 + cq + 4][16 * w + r    ];
            a[3] = Wsm[ks * 8 + cq + 4][16 * w + r + 8];
#pragma unroll
            for (int nt = 0; nt < 8; nt++) {
                u32 b[2];
                b[0] = Xsm[ks * 8 + cq    ][nt * 8 + r];
                b[1] = Xsm[ks * 8 + cq + 4][nt * 8 + r];
                mma_tf32(acc[nt], a, b);
            }
        }
        __syncthreads();
    }

    int row0 = m0 + 16 * w + r;
    int row1 = row0 + 8;
    float sc0 = gg[row0] * rsqrtf(vv[row0] + EPSBN);
    float bi0 = bb[row0] - mm[row0] * sc0;
    float sc1 = gg[row1] * rsqrtf(vv[row1] + EPSBN);
    float bi1 = bb[row1] - mm[row1] * sc1;
#pragma unroll
    for (int nt = 0; nt < 8; nt++) {
        int col = n0 + nt * 8 + 2 * cq;
        float2 o0 = make_float2(acc[nt][0] * sc0 + bi0, acc[nt][1] * sc0 + bi0);
        float2 o1 = make_float2(acc[nt][2] * sc1 + bi1, acc[nt][3] * sc1 + bi1);
        *(float2*)&Ob[(size_t)row0 * NPIX + col] = o0;
        *(float2*)&Ob[(size_t)row1 * NPIX + col] = o1;
    }
}

// ---------------------------------------------------------------------------
// Flash attention, tf32 mma, 256 threads (8 warps) = 128 queries per block.
// cp.async double-buffered K/V staging (raw fp32 bits -> tf32 truncation).
// Grid = (NPIX/128, BATCH*HEADS). Dynamic smem 88064 B.
// ---------------------------------------------------------------------------
#define KS_STRIDE 72
#define VS_STRIDE 68
#define KS_FLOATS (32 * KS_STRIDE)      // 2304
#define VS_FLOATS (64 * VS_STRIDE)      // 4352
#define OFF_KS0 0
#define OFF_KS1 (KS_FLOATS)
#define OFF_VS0 (2 * KS_FLOATS)
#define OFF_VS1 (2 * KS_FLOATS + VS_FLOATS)
#define OFF_PS  (2 * KS_FLOATS + 2 * VS_FLOATS)
#define ATT_SMEM_BYTES ((OFF_PS + 128 * VS_STRIDE) * 4)   // 88064

__global__ __launch_bounds__(256, 2) void attn_mma_kernel()
{
    extern __shared__ float smem[];
    const int bh = blockIdx.y;
    const int b  = bh >> 2;
    const int h  = bh & 3;
    const float* base  = g_qkv + ((size_t)b * HIDDEN + h * 128) * NPIX;
    const float* kbase = base + 32 * NPIX;
    const float* vbase = base + 64 * NPIX;

    const int i0   = blockIdx.x * 128;
    const int t    = threadIdx.x;
    const int w    = t >> 5;
    const int lane = t & 31;
    const int r    = lane >> 2;
    const int cq   = lane & 3;

    float* Ps = smem + OFF_PS;
    const u32 smem_base = (u32)__cvta_generic_to_shared(smem);

    const float QSCALE = 0.17677669529663687f * 1.4426950408889634f;

    // Q fragments, loaded once (rna-rounded).
    u32 qa[4][4];
    {
        int row0 = i0 + 16 * w + r;
#pragma unroll
        for (int ks = 0; ks < 4; ks++) {
            int d0 = ks * 8;
            qa[ks][0] = cvt_tf32(base[(size_t)(d0 + cq)     * NPIX + row0    ] * QSCALE);
            qa[ks][1] = cvt_tf32(base[(size_t)(d0 + cq)     * NPIX + row0 + 8] * QSCALE);
            qa[ks][2] = cvt_tf32(base[(size_t)(d0 + cq + 4) * NPIX + row0    ] * QSCALE);
            qa[ks][3] = cvt_tf32(base[(size_t)(d0 + cq + 4) * NPIX + row0 + 8] * QSCALE);
        }
    }

    float o[8][4];
#pragma unroll
    for (int nt = 0; nt < 8; nt++)
#pragma unroll
        for (int k = 0; k < 4; k++) o[nt][k] = 0.f;
    float m0 = -1e30f, m1 = -1e30f, l0 = 0.f, l1 = 0.f;

    // Staging lambda-equivalent (macro-free, inlined twice)
    // K tile: 512 float4; V tile: 1024 float4; 256 threads.
#define STAGE_TILE(kb, buf)                                                      \
    do {                                                                         \
        u32 ks_dst = smem_base + ((buf) ? OFF_KS1 : OFF_KS0) * 4;                \
        u32 vs_dst = smem_base + ((buf) ? OFF_VS1 : OFF_VS0) * 4;                \
        _Pragma("unroll")                                                        \
        for (int c = 0; c < 2; c++) {                                            \
            int idx = t + c * 256;                                               \
            int d = idx >> 4, j4 = (idx & 15) * 4;                               \
            cp16(ks_dst + (d * KS_STRIDE + j4) * 4,                              \
                 &kbase[(size_t)d * NPIX + (kb) + j4]);                          \
        }                                                                        \
        _Pragma("unroll")                                                        \
        for (int c = 0; c < 4; c++) {                                            \
            int idx = t + c * 256;                                               \
            int dv = idx >> 4, j4 = (idx & 15) * 4;                              \
            cp16(vs_dst + (dv * VS_STRIDE + j4) * 4,                             \
                 &vbase[(size_t)dv * NPIX + (kb) + j4]);                         \
        }                                                                        \
        cp_commit();                                                             \
    } while (0)

    STAGE_TILE(0, 0);

    for (int tt = 0; tt < 64; tt++) {
        cp_wait0();
        __syncthreads();
        if (tt < 63) STAGE_TILE((tt + 1) * 64, (tt + 1) & 1);

        const float* Ks = smem + ((tt & 1) ? OFF_KS1 : OFF_KS0);
        const float* Vs = smem + ((tt & 1) ? OFF_VS1 : OFF_VS0);

        // ---- S = Q * K^T ----
        float s[8][4];
#pragma unroll
        for (int nt = 0; nt < 8; nt++)
#pragma unroll
            for (int k = 0; k < 4; k++) s[nt][k] = 0.f;
#pragma unroll
        for (int ks = 0; ks < 4; ks++) {
#pragma unroll
            for (int nt = 0; nt < 8; nt++) {
                u32 bf[2];
                bf[0] = __float_as_uint(Ks[(ks * 8 + cq    ) * KS_STRIDE + nt * 8 + r]);
                bf[1] = __float_as_uint(Ks[(ks * 8 + cq + 4) * KS_STRIDE + nt * 8 + r]);
                mma_tf32(s[nt], qa[ks], bf);
            }
        }

        // ---- online softmax ----
        float mx0 = m0, mx1 = m1;
#pragma unroll
        for (int nt = 0; nt < 8; nt++) {
            mx0 = fmaxf(mx0, fmaxf(s[nt][0], s[nt][1]));
            mx1 = fmaxf(mx1, fmaxf(s[nt][2], s[nt][3]));
        }
        mx0 = fmaxf(mx0, __shfl_xor_sync(0xffffffffu, mx0, 1));
        mx0 = fmaxf(mx0, __shfl_xor_sync(0xffffffffu, mx0, 2));
        mx1 = fmaxf(mx1, __shfl_xor_sync(0xffffffffu, mx1, 1));
        mx1 = fmaxf(mx1, __shfl_xor_sync(0xffffffffu, mx1, 2));
        float corr0 = ex2(m0 - mx0);
        float corr1 = ex2(m1 - mx1);
        m0 = mx0; m1 = mx1;

        float ps0 = 0.f, ps1 = 0.f;
#pragma unroll
        for (int nt = 0; nt < 8; nt++) {
            s[nt][0] = ex2(s[nt][0] - m0);
            s[nt][1] = ex2(s[nt][1] - m0);
            s[nt][2] = ex2(s[nt][2] - m1);
            s[nt][3] = ex2(s[nt][3] - m1);
            ps0 += s[nt][0] + s[nt][1];
            ps1 += s[nt][2] + s[nt][3];
        }
        ps0 += __shfl_xor_sync(0xffffffffu, ps0, 1);
        ps0 += __shfl_xor_sync(0xffffffffu, ps0, 2);
        ps1 += __shfl_xor_sync(0xffffffffu, ps1, 1);
        ps1 += __shfl_xor_sync(0xffffffffu, ps1, 2);
        l0 = l0 * corr0 + ps0;
        l1 = l1 * corr1 + ps1;

#pragma unroll
        for (int nt = 0; nt < 8; nt++) {
            o[nt][0] *= corr0; o[nt][1] *= corr0;
            o[nt][2] *= corr1; o[nt][3] *= corr1;
        }

        // ---- write P (warp-private rows, raw fp32 bits) ----
#pragma unroll
        for (int nt = 0; nt < 8; nt++) {
            *(float2*)&Ps[(16 * w + r    ) * VS_STRIDE + nt * 8 + 2 * cq] = make_float2(s[nt][0], s[nt][1]);
            *(float2*)&Ps[(16 * w + r + 8) * VS_STRIDE + nt * 8 + 2 * cq] = make_float2(s[nt][2], s[nt][3]);
        }
        __syncwarp();

        // ---- O += P * V ----
#pragma unroll
        for (int ks2 = 0; ks2 < 8; ks2++) {
            u32 pa[4];
            pa[0] = __float_as_uint(Ps[(16 * w + r    ) * VS_STRIDE + ks2 * 8 + cq    ]);
            pa[1] = __float_as_uint(Ps[(16 * w + r + 8) * VS_STRIDE + ks2 * 8 + cq    ]);
            pa[2] = __float_as_uint(Ps[(16 * w + r    ) * VS_STRIDE + ks2 * 8 + cq + 4]);
            pa[3] = __float_as_uint(Ps[(16 * w + r + 8) * VS_STRIDE + ks2 * 8 + cq + 4]);
#pragma unroll
            for (int nt = 0; nt < 8; nt++) {
                u32 bf[2];
                bf[0] = __float_as_uint(Vs[(nt * 8 + r) * VS_STRIDE + ks2 * 8 + cq    ]);
                bf[1] = __float_as_uint(Vs[(nt * 8 + r) * VS_STRIDE + ks2 * 8 + cq + 4]);
                mma_tf32(o[nt], pa, bf);
            }
        }
        __syncwarp();
    }

    // ---- epilogue ----
    float inv0 = 1.f / l0;
    float inv1 = 1.f / l1;
    float* ybase = g_y + ((size_t)b * DIMC + h * 64) * NPIX;
    int row0 = i0 + 16 * w + r;
    int row1 = row0 + 8;
#pragma unroll
    for (int nt = 0; nt < 8; nt++) {
        int dv0 = nt * 8 + 2 * cq;
        ybase[(size_t)(dv0    ) * NPIX + row0] = o[nt][0] * inv0;
        ybase[(size_t)(dv0 + 1) * NPIX + row0] = o[nt][1] * inv0;
        ybase[(size_t)(dv0    ) * NPIX + row1] = o[nt][2] * inv1;
        ybase[(size_t)(dv0 + 1) * NPIX + row1] = o[nt][3] * inv1;
    }
}

// ---------------------------------------------------------------------------
// Depthwise 3x3 conv (pad 1) on V image + BN, added into g_y.
// ---------------------------------------------------------------------------
__global__ __launch_bounds__(256) void pe_add_kernel(
    const float* __restrict__ pw, const float* __restrict__ pg,
    const float* __restrict__ pb, const float* __restrict__ pm,
    const float* __restrict__ pv)
{
    int idx = blockIdx.x * 256 + threadIdx.x;
    if (idx >= BATCH * DIMC * NPIX) return;
    int n = idx & 4095;
    int c = (idx >> 12) & 255;
    int b = idx >> 20;
    int yy = n >> 6, xx = n & 63;

    int vrow = (c >> 6) * 128 + 64 + (c & 63);
    const float* vimg = g_qkv + ((size_t)b * HIDDEN + vrow) * NPIX;

    float sum = 0.f;
#pragma unroll
    for (int ky = 0; ky < 3; ky++) {
        int y2 = yy + ky - 1;
        if (y2 < 0 || y2 >= HWDIM) continue;
#pragma unroll
        for (int kx = 0; kx < 3; kx++) {
            int x2 = xx + kx - 1;
            if (x2 < 0 || x2 >= HWDIM) continue;
            sum += pw[c * 9 + ky * 3 + kx] * vimg[y2 * HWDIM + x2];
        }
    }
    float sc = pg[c] * rsqrtf(pv[c] + EPSBN);
    g_y[idx] += sum * sc + (pb[c] - pm[c] * sc);
}

// ---------------------------------------------------------------------------
extern "C" void kernel_launch(void* const* d_in, const int* in_sizes, int n_in,
                              void* d_out, int out_size)
{
    const float* x      = (const float*)d_in[0];
    const float* qkv_w  = (const float*)d_in[1];
    const float* qkv_g  = (const float*)d_in[2];
    const float* qkv_b  = (const float*)d_in[3];
    const float* qkv_m  = (const float*)d_in[4];
    const float* qkv_v  = (const float*)d_in[5];
    const float* proj_w = (const float*)d_in[6];
    const float* proj_g = (const float*)d_in[7];
    const float* proj_b = (const float*)d_in[8];
    const float* proj_m = (const float*)d_in[9];
    const float* proj_v = (const float*)d_in[10];
    const float* pe_w   = (const float*)d_in[11];
    const float* pe_g   = (const float*)d_in[12];
    const float* pe_b   = (const float*)d_in[13];
    const float* pe_m   = (const float*)d_in[14];
    const float* pe_v   = (const float*)d_in[15];
    float* out = (float*)d_out;

    static float* qkv_buf = nullptr;
    static float* y_buf   = nullptr;
    if (!qkv_buf) {
        cudaGetSymbolAddress((void**)&qkv_buf, g_qkv);
        cudaGetSymbolAddress((void**)&y_buf,   g_y);
        cudaFuncSetAttribute(attn_mma_kernel,
                             cudaFuncAttributeMaxDynamicSharedMemorySize,
                             ATT_SMEM_BYTES);
    }

    // 1) QKV 1x1 conv + BN : [512,256] x [256,4096] per batch
    {
        dim3 grid(NPIX / 64, HIDDEN / 64, BATCH);
        gemm_mma_kernel<<<grid, 128>>>(x, qkv_w, qkv_g, qkv_b, qkv_m, qkv_v,
                                       qkv_buf, HIDDEN, DIMC);
    }
    // 2) Attention (tensor-core tf32, cp.async pipelined)
    {
        dim3 grid(NPIX / 128, BATCH * HEADS);
        attn_mma_kernel<<<grid, 256, ATT_SMEM_BYTES>>>();
    }
    // 3) PE depthwise conv + BN, add into y
    {
        int total = BATCH * DIMC * NPIX;
        pe_add_kernel<<<(total + 255) / 256, 256>>>(pe_w, pe_g, pe_b, pe_m, pe_v);
    }
    // 4) proj 1x1 conv + BN : [256,256] x [256,4096] per batch -> out
    {
        dim3 grid(NPIX / 64, DIMC / 64, BATCH);
        gemm_mma_kernel<<<grid, 128>>>(y_buf, proj_g ? proj_w : proj_w, proj_g, proj_b, proj_m, proj_v,
                                       out, DIMC, DIMC);
    }
}

// round 6
// speedup vs baseline: 4.2192x; 1.1818x over previous
#include <cuda_runtime.h>
#include <math.h>

#define DIMC   256
#define HEADS  4
#define HEAD_DIM 64
#define KEY_DIM  32
#define HIDDEN 512
#define BATCH  2
#define NPIX   4096
#define HWDIM  64
#define EPSBN  1e-5f

typedef unsigned long long u64;
typedef unsigned int u32;

__device__ __forceinline__ float ex2(float x) {
    float y; asm("ex2.approx.ftz.f32 %0, %1;" : "=f"(y) : "f"(x));
    return y;
}
__device__ __forceinline__ u32 cvt_tf32(float x) {
    u32 u; asm("cvt.rna.tf32.f32 %0, %1;" : "=r"(u) : "f"(x));
    return u;
}
// D += A(tf32 m16k8) * B(tf32 k8n8)
__device__ __forceinline__ void mma_tf32(float c[4], const u32 a[4], const u32 b[2]) {
    asm("mma.sync.aligned.m16n8k8.row.col.f32.tf32.tf32.f32 "
        "{%0,%1,%2,%3},{%4,%5,%6,%7},{%8,%9},{%0,%1,%2,%3};"
        : "+f"(c[0]), "+f"(c[1]), "+f"(c[2]), "+f"(c[3])
        : "r"(a[0]), "r"(a[1]), "r"(a[2]), "r"(a[3]), "r"(b[0]), "r"(b[1]));
}
__device__ __forceinline__ void cp16(u32 dst, const void* src) {
    asm volatile("cp.async.ca.shared.global [%0], [%1], 16;" :: "r"(dst), "l"(src));
}
__device__ __forceinline__ void cp_commit() {
    asm volatile("cp.async.commit_group;" ::: "memory");
}
__device__ __forceinline__ void cp_wait0() {
    asm volatile("cp.async.wait_group 0;" ::: "memory");
}

// Scratch (allocation-free rule: __device__ globals)
__device__ float g_qkv[BATCH * HIDDEN * NPIX]; // 16 MB
__device__ float g_y  [BATCH * DIMC  * NPIX];  //  8 MB

// ---------------------------------------------------------------------------
// tf32 tensor-core GEMM + folded BN, tile M=128 x N=64, K-chunk 32.
// cp.async double-buffered. 128 threads (4 warps); warp w owns m-rows
// [16w,16w+16) and [64+16w, 64+16w+16) (B-fragments shared across the two).
// cvt.rna applied at consume for full accuracy.
// ---------------------------------------------------------------------------
#define GW_STR 36
#define GX_STR 72
#define GW_FLOATS (128 * GW_STR)            // 4608
#define GX_FLOATS (32 * GX_STR)             // 2304
#define OFF_W0 0
#define OFF_W1 GW_FLOATS
#define OFF_X0 (2 * GW_FLOATS)
#define OFF_X1 (2 * GW_FLOATS + GX_FLOATS)
#define GEMM_SMEM_BYTES ((2 * GW_FLOATS + 2 * GX_FLOATS) * 4)  // 55296

__global__ __launch_bounds__(128) void gemm_mma_kernel(
    const float* __restrict__ X, const float* __restrict__ W,
    const float* __restrict__ gg, const float* __restrict__ bb,
    const float* __restrict__ mm, const float* __restrict__ vv,
    float* __restrict__ Out, int M, int K)
{
    extern __shared__ float gsm[];
    const int n0 = blockIdx.x * 64;
    const int m0 = blockIdx.y * 128;
    const int bz = blockIdx.z;
    const float* Xb = X + (size_t)bz * K * NPIX;
    float*       Ob = Out + (size_t)bz * M * NPIX;

    const int t    = threadIdx.x;
    const int w    = t >> 5;
    const int lane = t & 31;
    const int r    = lane >> 2;
    const int cq   = lane & 3;
    const u32 smb  = (u32)__cvta_generic_to_shared(gsm);

    float acc[2][8][4];
#pragma unroll
    for (int g = 0; g < 2; g++)
#pragma unroll
        for (int nt = 0; nt < 8; nt++)
#pragma unroll
            for (int k = 0; k < 4; k++) acc[g][nt][k] = 0.f;

#define STAGE_G(k0, buf)                                                        \
    do {                                                                        \
        u32 wd = smb + ((buf) ? OFF_W1 : OFF_W0) * 4;                           \
        u32 xd = smb + ((buf) ? OFF_X1 : OFF_X0) * 4;                           \
        _Pragma("unroll")                                                       \
        for (int c = 0; c < 8; c++) {                                           \
            int idx = t + c * 128;                                              \
            int m = idx >> 3, kc = idx & 7;                                     \
            cp16(wd + (m * GW_STR + kc * 4) * 4,                                \
                 &W[(size_t)(m0 + m) * K + (k0) + kc * 4]);                     \
        }                                                                       \
        _Pragma("unroll")                                                       \
        for (int c = 0; c < 4; c++) {                                           \
            int idx = t + c * 128;                                              \
            int kk = idx >> 4, n4 = (idx & 15) * 4;                             \
            cp16(xd + (kk * GX_STR + n4) * 4,                                   \
                 &Xb[(size_t)((k0) + kk) * NPIX + n0 + n4]);                    \
        }                                                                       \
        cp_commit();                                                            \
    } while (0)

    STAGE_G(0, 0);
    const int nchunks = K / 32;
    for (int c0 = 0; c0 < nchunks; c0++) {
        cp_wait0();
        __syncthreads();
        if (c0 < nchunks - 1) STAGE_G((c0 + 1) * 32, (c0 + 1) & 1);

        const float* Wt = gsm + ((c0 & 1) ? OFF_W1 : OFF_W0);
        const float* Xs = gsm + ((c0 & 1) ? OFF_X1 : OFF_X0);
#pragma unroll
        for (int ks = 0; ks < 4; ks++) {
            u32 a[2][4];
#pragma unroll
            for (int g = 0; g < 2; g++) {
                int mr = 64 * g + 16 * w + r;
                a[g][0] = cvt_tf32(Wt[(mr    ) * GW_STR + ks * 8 + cq    ]);
                a[g][1] = cvt_tf32(Wt[(mr + 8) * GW_STR + ks * 8 + cq    ]);
                a[g][2] = cvt_tf32(Wt[(mr    ) * GW_STR + ks * 8 + cq + 4]);
                a[g][3] = cvt_tf32(Wt[(mr + 8) * GW_STR + ks * 8 + cq + 4]);
            }
#pragma unroll
            for (int nt = 0; nt < 8; nt++) {
                u32 b[2];
                b[0] = cvt_tf32(Xs[(ks * 8 + cq    ) * GX_STR + nt * 8 + r]);
                b[1] = cvt_tf32(Xs[(ks * 8 + cq + 4) * GX_STR + nt * 8 + r]);
                mma_tf32(acc[0][nt], a[0], b);
                mma_tf32(acc[1][nt], a[1], b);
            }
        }
    }

#pragma unroll
    for (int g = 0; g < 2; g++) {
        int row0 = m0 + 64 * g + 16 * w + r;
        int row1 = row0 + 8;
        float sc0 = gg[row0] * rsqrtf(vv[row0] + EPSBN);
        float bi0 = bb[row0] - mm[row0] * sc0;
        float sc1 = gg[row1] * rsqrtf(vv[row1] + EPSBN);
        float bi1 = bb[row1] - mm[row1] * sc1;
#pragma unroll
        for (int nt = 0; nt < 8; nt++) {
            int col = n0 + nt * 8 + 2 * cq;
            *(float2*)&Ob[(size_t)row0 * NPIX + col] =
                make_float2(acc[g][nt][0] * sc0 + bi0, acc[g][nt][1] * sc0 + bi0);
            *(float2*)&Ob[(size_t)row1 * NPIX + col] =
                make_float2(acc[g][nt][2] * sc1 + bi1, acc[g][nt][3] * sc1 + bi1);
        }
    }
}

// ---------------------------------------------------------------------------
// Flash attention, tf32 mma. 128 threads (4 warps); each warp owns 32 queries
// (two 16-row tiles) so V B-fragments are shared across 2 mma.
// cp.async double-buffered K/V staging. P stored rna; V rna at consume.
// Grid = (NPIX/128, BATCH*HEADS).
// ---------------------------------------------------------------------------
#define KS_STRIDE 72
#define VS_STRIDE 68
#define KS_FLOATS (32 * KS_STRIDE)      // 2304
#define VS_FLOATS (64 * VS_STRIDE)      // 4352
#define OFF_KS0 0
#define OFF_KS1 (KS_FLOATS)
#define OFF_VS0 (2 * KS_FLOATS)
#define OFF_VS1 (2 * KS_FLOATS + VS_FLOATS)
#define OFF_PS  (2 * KS_FLOATS + 2 * VS_FLOATS)
#define ATT_SMEM_BYTES ((OFF_PS + 128 * VS_STRIDE) * 4)   // 88064

__global__ __launch_bounds__(128) void attn_mma_kernel()
{
    extern __shared__ float smem[];
    const int bh = blockIdx.y;
    const int b  = bh >> 2;
    const int h  = bh & 3;
    const float* base  = g_qkv + ((size_t)b * HIDDEN + h * 128) * NPIX;
    const float* kbase = base + 32 * NPIX;
    const float* vbase = base + 64 * NPIX;

    const int i0   = blockIdx.x * 128;
    const int t    = threadIdx.x;
    const int w    = t >> 5;
    const int lane = t & 31;
    const int r    = lane >> 2;
    const int cq   = lane & 3;

    float* Ps = smem + OFF_PS;
    const u32 smb = (u32)__cvta_generic_to_shared(smem);

    const float QSCALE = 0.17677669529663687f * 1.4426950408889634f;

    // Q fragments for 2 row-tiles (rna).
    u32 qa[2][4][4];
#pragma unroll
    for (int rt = 0; rt < 2; rt++) {
        int row0 = i0 + 32 * w + 16 * rt + r;
#pragma unroll
        for (int ks = 0; ks < 4; ks++) {
            int d0 = ks * 8;
            qa[rt][ks][0] = cvt_tf32(base[(size_t)(d0 + cq)     * NPIX + row0    ] * QSCALE);
            qa[rt][ks][1] = cvt_tf32(base[(size_t)(d0 + cq)     * NPIX + row0 + 8] * QSCALE);
            qa[rt][ks][2] = cvt_tf32(base[(size_t)(d0 + cq + 4) * NPIX + row0    ] * QSCALE);
            qa[rt][ks][3] = cvt_tf32(base[(size_t)(d0 + cq + 4) * NPIX + row0 + 8] * QSCALE);
        }
    }

    float o[2][8][4];
#pragma unroll
    for (int rt = 0; rt < 2; rt++)
#pragma unroll
        for (int nt = 0; nt < 8; nt++)
#pragma unroll
            for (int k = 0; k < 4; k++) o[rt][nt][k] = 0.f;
    float mx[2][2] = {{-1e30f, -1e30f}, {-1e30f, -1e30f}};
    float ll[2][2] = {{0.f, 0.f}, {0.f, 0.f}};

#define STAGE_TILE(kb, buf)                                                      \
    do {                                                                         \
        u32 ks_dst = smb + ((buf) ? OFF_KS1 : OFF_KS0) * 4;                      \
        u32 vs_dst = smb + ((buf) ? OFF_VS1 : OFF_VS0) * 4;                      \
        _Pragma("unroll")                                                        \
        for (int c = 0; c < 4; c++) {                                            \
            int idx = t + c * 128;                                               \
            int d = idx >> 4, j4 = (idx & 15) * 4;                               \
            cp16(ks_dst + (d * KS_STRIDE + j4) * 4,                              \
                 &kbase[(size_t)d * NPIX + (kb) + j4]);                          \
        }                                                                        \
        _Pragma("unroll")                                                        \
        for (int c = 0; c < 8; c++) {                                            \
            int idx = t + c * 128;                                               \
            int dv = idx >> 4, j4 = (idx & 15) * 4;                              \
            cp16(vs_dst + (dv * VS_STRIDE + j4) * 4,                             \
                 &vbase[(size_t)dv * NPIX + (kb) + j4]);                         \
        }                                                                        \
        cp_commit();                                                             \
    } while (0)

    STAGE_TILE(0, 0);

    for (int tt = 0; tt < 64; tt++) {
        cp_wait0();
        __syncthreads();
        if (tt < 63) STAGE_TILE((tt + 1) * 64, (tt + 1) & 1);

        const float* Ks = smem + ((tt & 1) ? OFF_KS1 : OFF_KS0);
        const float* Vs = smem + ((tt & 1) ? OFF_VS1 : OFF_VS0);

        // ---- S, softmax, P per row-tile ----
#pragma unroll
        for (int rt = 0; rt < 2; rt++) {
            float s[8][4];
#pragma unroll
            for (int nt = 0; nt < 8; nt++)
#pragma unroll
                for (int k = 0; k < 4; k++) s[nt][k] = 0.f;
#pragma unroll
            for (int ks = 0; ks < 4; ks++) {
#pragma unroll
                for (int nt = 0; nt < 8; nt++) {
                    u32 bf[2];
                    bf[0] = __float_as_uint(Ks[(ks * 8 + cq    ) * KS_STRIDE + nt * 8 + r]);
                    bf[1] = __float_as_uint(Ks[(ks * 8 + cq + 4) * KS_STRIDE + nt * 8 + r]);
                    mma_tf32(s[nt], qa[rt][ks], bf);
                }
            }

            float mx0 = mx[rt][0], mx1 = mx[rt][1];
#pragma unroll
            for (int nt = 0; nt < 8; nt++) {
                mx0 = fmaxf(mx0, fmaxf(s[nt][0], s[nt][1]));
                mx1 = fmaxf(mx1, fmaxf(s[nt][2], s[nt][3]));
            }
            mx0 = fmaxf(mx0, __shfl_xor_sync(0xffffffffu, mx0, 1));
            mx0 = fmaxf(mx0, __shfl_xor_sync(0xffffffffu, mx0, 2));
            mx1 = fmaxf(mx1, __shfl_xor_sync(0xffffffffu, mx1, 1));
            mx1 = fmaxf(mx1, __shfl_xor_sync(0xffffffffu, mx1, 2));
            float corr0 = ex2(mx[rt][0] - mx0);
            float corr1 = ex2(mx[rt][1] - mx1);
            mx[rt][0] = mx0; mx[rt][1] = mx1;

            float ps0 = 0.f, ps1 = 0.f;
#pragma unroll
            for (int nt = 0; nt < 8; nt++) {
                s[nt][0] = ex2(s[nt][0] - mx0);
                s[nt][1] = ex2(s[nt][1] - mx0);
                s[nt][2] = ex2(s[nt][2] - mx1);
                s[nt][3] = ex2(s[nt][3] - mx1);
                ps0 += s[nt][0] + s[nt][1];
                ps1 += s[nt][2] + s[nt][3];
            }
            ps0 += __shfl_xor_sync(0xffffffffu, ps0, 1);
            ps0 += __shfl_xor_sync(0xffffffffu, ps0, 2);
            ps1 += __shfl_xor_sync(0xffffffffu, ps1, 1);
            ps1 += __shfl_xor_sync(0xffffffffu, ps1, 2);
            ll[rt][0] = ll[rt][0] * corr0 + ps0;
            ll[rt][1] = ll[rt][1] * corr1 + ps1;

#pragma unroll
            for (int nt = 0; nt < 8; nt++) {
                o[rt][nt][0] *= corr0; o[rt][nt][1] *= corr0;
                o[rt][nt][2] *= corr1; o[rt][nt][3] *= corr1;
            }

            // P: rna-convert then store (removes truncation bias)
            int pr0 = 32 * w + 16 * rt + r;
#pragma unroll
            for (int nt = 0; nt < 8; nt++) {
                *(float2*)&Ps[(pr0    ) * VS_STRIDE + nt * 8 + 2 * cq] =
                    make_float2(__uint_as_float(cvt_tf32(s[nt][0])),
                                __uint_as_float(cvt_tf32(s[nt][1])));
                *(float2*)&Ps[(pr0 + 8) * VS_STRIDE + nt * 8 + 2 * cq] =
                    make_float2(__uint_as_float(cvt_tf32(s[nt][2])),
                                __uint_as_float(cvt_tf32(s[nt][3])));
            }
        }
        __syncwarp();

        // ---- O += P * V  (V B-fragments shared across both row-tiles) ----
#pragma unroll
        for (int ks2 = 0; ks2 < 8; ks2++) {
            u32 pa[2][4];
#pragma unroll
            for (int rt = 0; rt < 2; rt++) {
                int pr0 = 32 * w + 16 * rt + r;
                pa[rt][0] = __float_as_uint(Ps[(pr0    ) * VS_STRIDE + ks2 * 8 + cq    ]);
                pa[rt][1] = __float_as_uint(Ps[(pr0 + 8) * VS_STRIDE + ks2 * 8 + cq    ]);
                pa[rt][2] = __float_as_uint(Ps[(pr0    ) * VS_STRIDE + ks2 * 8 + cq + 4]);
                pa[rt][3] = __float_as_uint(Ps[(pr0 + 8) * VS_STRIDE + ks2 * 8 + cq + 4]);
            }
#pragma unroll
            for (int nt = 0; nt < 8; nt++) {
                u32 bf[2];
                bf[0] = cvt_tf32(Vs[(nt * 8 + r) * VS_STRIDE + ks2 * 8 + cq    ]);
                bf[1] = cvt_tf32(Vs[(nt * 8 + r) * VS_STRIDE + ks2 * 8 + cq + 4]);
                mma_tf32(o[0][nt], pa[0], bf);
                mma_tf32(o[1][nt], pa[1], bf);
            }
        }
        __syncwarp();
    }

    // ---- epilogue ----
    float* ybase = g_y + ((size_t)b * DIMC + h * 64) * NPIX;
#pragma unroll
    for (int rt = 0; rt < 2; rt++) {
        float inv0 = 1.f / ll[rt][0];
        float inv1 = 1.f / ll[rt][1];
        int row0 = i0 + 32 * w + 16 * rt + r;
        int row1 = row0 + 8;
#pragma unroll
        for (int nt = 0; nt < 8; nt++) {
            int dv0 = nt * 8 + 2 * cq;
            ybase[(size_t)(dv0    ) * NPIX + row0] = o[rt][nt][0] * inv0;
            ybase[(size_t)(dv0 + 1) * NPIX + row0] = o[rt][nt][1] * inv0;
            ybase[(size_t)(dv0    ) * NPIX + row1] = o[rt][nt][2] * inv1;
            ybase[(size_t)(dv0 + 1) * NPIX + row1] = o[rt][nt][3] * inv1;
        }
    }
}

// ---------------------------------------------------------------------------
// Depthwise 3x3 conv (pad 1) on V image + BN, added into g_y.
// ---------------------------------------------------------------------------
__global__ __launch_bounds__(256) void pe_add_kernel(
    const float* __restrict__ pw, const float* __restrict__ pg,
    const float* __restrict__ pb, const float* __restrict__ pm,
    const float* __restrict__ pv)
{
    int idx = blockIdx.x * 256 + threadIdx.x;
    if (idx >= BATCH * DIMC * NPIX) return;
    int n = idx & 4095;
    int c = (idx >> 12) & 255;
    int b = idx >> 20;
    int yy = n >> 6, xx = n & 63;

    int vrow = (c >> 6) * 128 + 64 + (c & 63);
    const float* vimg = g_qkv + ((size_t)b * HIDDEN + vrow) * NPIX;

    float sum = 0.f;
#pragma unroll
    for (int ky = 0; ky < 3; ky++) {
        int y2 = yy + ky - 1;
        if (y2 < 0 || y2 >= HWDIM) continue;
#pragma unroll
        for (int kx = 0; kx < 3; kx++) {
            int x2 = xx + kx - 1;
            if (x2 < 0 || x2 >= HWDIM) continue;
            sum += pw[c * 9 + ky * 3 + kx] * vimg[y2 * HWDIM + x2];
        }
    }
    float sc = pg[c] * rsqrtf(pv[c] + EPSBN);
    g_y[idx] += sum * sc + (pb[c] - pm[c] * sc);
}

// ---------------------------------------------------------------------------
extern "C" void kernel_launch(void* const* d_in, const int* in_sizes, int n_in,
                              void* d_out, int out_size)
{
    const float* x      = (const float*)d_in[0];
    const float* qkv_w  = (const float*)d_in[1];
    const float* qkv_g  = (const float*)d_in[2];
    const float* qkv_b  = (const float*)d_in[3];
    const float* qkv_m  = (const float*)d_in[4];
    const float* qkv_v  = (const float*)d_in[5];
    const float* proj_w = (const float*)d_in[6];
    const float* proj_g = (const float*)d_in[7];
    const float* proj_b = (const float*)d_in[8];
    const float* proj_m = (const float*)d_in[9];
    const float* proj_v = (const float*)d_in[10];
    const float* pe_w   = (const float*)d_in[11];
    const float* pe_g   = (const float*)d_in[12];
    const float* pe_b   = (const float*)d_in[13];
    const float* pe_m   = (const float*)d_in[14];
    const float* pe_v   = (const float*)d_in[15];
    float* out = (float*)d_out;

    static float* qkv_buf = nullptr;
    static float* y_buf   = nullptr;
    if (!qkv_buf) {
        cudaGetSymbolAddress((void**)&qkv_buf, g_qkv);
        cudaGetSymbolAddress((void**)&y_buf,   g_y);
        cudaFuncSetAttribute(attn_mma_kernel,
                             cudaFuncAttributeMaxDynamicSharedMemorySize,
                             ATT_SMEM_BYTES);
        cudaFuncSetAttribute(gemm_mma_kernel,
                             cudaFuncAttributeMaxDynamicSharedMemorySize,
                             GEMM_SMEM_BYTES);
    }

    // 1) QKV 1x1 conv + BN : [512,256] x [256,4096] per batch
    {
        dim3 grid(NPIX / 64, HIDDEN / 128, BATCH);
        gemm_mma_kernel<<<grid, 128, GEMM_SMEM_BYTES>>>(
            x, qkv_w, qkv_g, qkv_b, qkv_m, qkv_v, qkv_buf, HIDDEN, DIMC);
    }
    // 2) Attention (tf32 mma, 32q/warp, cp.async pipelined)
    {
        dim3 grid(NPIX / 128, BATCH * HEADS);
        attn_mma_kernel<<<grid, 128, ATT_SMEM_BYTES>>>();
    }
    // 3) PE depthwise conv + BN, add into y
    {
        int total = BATCH * DIMC * NPIX;
        pe_add_kernel<<<(total + 255) / 256, 256>>>(pe_w, pe_g, pe_b, pe_m, pe_v);
    }
    // 4) proj 1x1 conv + BN : [256,256] x [256,4096] per batch -> out
    {
        dim3 grid(NPIX / 64, DIMC / 128, BATCH);
        gemm_mma_kernel<<<grid, 128, GEMM_SMEM_BYTES>>>(
            y_buf, proj_w, proj_g, proj_b, proj_m, proj_v, out, DIMC, DIMC);
    }
}

// round 8
// speedup vs baseline: 6.9610x; 1.6498x over previous
#include <cuda_runtime.h>
#include <cuda_fp16.h>
#include <math.h>

#define DIMC   256
#define HEADS  4
#define HEAD_DIM 64
#define KEY_DIM  32
#define HIDDEN 512
#define BATCH  2
#define NPIX   4096
#define HWDIM  64
#define EPSBN  1e-5f

typedef unsigned long long u64;
typedef unsigned int u32;

__device__ __forceinline__ float ex2(float x) {
    float y; asm("ex2.approx.ftz.f32 %0, %1;" : "=f"(y) : "f"(x));
    return y;
}
__device__ __forceinline__ u32 cvt_tf32(float x) {
    u32 u; asm("cvt.rna.tf32.f32 %0, %1;" : "=r"(u) : "f"(x));
    return u;
}
// pack {lo, hi} floats -> f16x2 register
__device__ __forceinline__ u32 h2pack(float lo, float hi) {
    u32 d; asm("cvt.rn.f16x2.f32 %0, %1, %2;" : "=r"(d) : "f"(hi), "f"(lo));
    return d;
}
// D += A(f16 m16k16) * B(f16 k16n8), fp32 accum
__device__ __forceinline__ void mma_f16(float c[4], const u32 a[4], u32 b0, u32 b1) {
    asm("mma.sync.aligned.m16n8k16.row.col.f32.f16.f16.f32 "
        "{%0,%1,%2,%3},{%4,%5,%6,%7},{%8,%9},{%0,%1,%2,%3};"
        : "+f"(c[0]), "+f"(c[1]), "+f"(c[2]), "+f"(c[3])
        : "r"(a[0]), "r"(a[1]), "r"(a[2]), "r"(a[3]), "r"(b0), "r"(b1));
}
// D += A(tf32 m16k8) * B(tf32 k8n8)
__device__ __forceinline__ void mma_tf32(float c[4], const u32 a[4], const u32 b[2]) {
    asm("mma.sync.aligned.m16n8k8.row.col.f32.tf32.tf32.f32 "
        "{%0,%1,%2,%3},{%4,%5,%6,%7},{%8,%9},{%0,%1,%2,%3};"
        : "+f"(c[0]), "+f"(c[1]), "+f"(c[2]), "+f"(c[3])
        : "r"(a[0]), "r"(a[1]), "r"(a[2]), "r"(a[3]), "r"(b[0]), "r"(b[1]));
}
__device__ __forceinline__ void cp16(u32 dst, const void* src) {
    asm volatile("cp.async.ca.shared.global [%0], [%1], 16;" :: "r"(dst), "l"(src));
}
__device__ __forceinline__ void cp_commit() {
    asm volatile("cp.async.commit_group;" ::: "memory");
}
__device__ __forceinline__ void cp_wait0() {
    asm volatile("cp.async.wait_group 0;" ::: "memory");
}

// Scratch (allocation-free rule: __device__ globals)
__device__ float g_qkv[BATCH * HIDDEN * NPIX]; // 16 MB
__device__ float g_y  [BATCH * DIMC  * NPIX];  //  8 MB
__device__ __half g_q16[BATCH * HEADS * NPIX * KEY_DIM];   // [bh][n][d], QSCALE baked
__device__ __half g_k16[BATCH * HEADS * NPIX * KEY_DIM];   // [bh][n][d]
__device__ __half g_v16[BATCH * HEADS * HEAD_DIM * NPIX];  // [bh][dv][n]

// ---------------------------------------------------------------------------
// tf32 tensor-core GEMM + folded BN (round-6 design, unchanged).
// ---------------------------------------------------------------------------
#define GW_STR 36
#define GX_STR 72
#define GW_FLOATS (128 * GW_STR)
#define GX_FLOATS (32 * GX_STR)
#define OFF_W0 0
#define OFF_W1 GW_FLOATS
#define OFF_X0 (2 * GW_FLOATS)
#define OFF_X1 (2 * GW_FLOATS + GX_FLOATS)
#define GEMM_SMEM_BYTES ((2 * GW_FLOATS + 2 * GX_FLOATS) * 4)  // 55296

__global__ __launch_bounds__(128) void gemm_mma_kernel(
    const float* __restrict__ X, const float* __restrict__ W,
    const float* __restrict__ gg, const float* __restrict__ bb,
    const float* __restrict__ mm, const float* __restrict__ vv,
    float* __restrict__ Out, int M, int K)
{
    extern __shared__ float gsm[];
    const int n0 = blockIdx.x * 64;
    const int m0 = blockIdx.y * 128;
    const int bz = blockIdx.z;
    const float* Xb = X + (size_t)bz * K * NPIX;
    float*       Ob = Out + (size_t)bz * M * NPIX;

    const int t    = threadIdx.x;
    const int w    = t >> 5;
    const int lane = t & 31;
    const int r    = lane >> 2;
    const int cq   = lane & 3;
    const u32 smb  = (u32)__cvta_generic_to_shared(gsm);

    float acc[2][8][4];
#pragma unroll
    for (int g = 0; g < 2; g++)
#pragma unroll
        for (int nt = 0; nt < 8; nt++)
#pragma unroll
            for (int k = 0; k < 4; k++) acc[g][nt][k] = 0.f;

#define STAGE_G(k0, buf)                                                        \
    do {                                                                        \
        u32 wd = smb + ((buf) ? OFF_W1 : OFF_W0) * 4;                           \
        u32 xd = smb + ((buf) ? OFF_X1 : OFF_X0) * 4;                           \
        _Pragma("unroll")                                                       \
        for (int c = 0; c < 8; c++) {                                           \
            int idx = t + c * 128;                                              \
            int m = idx >> 3, kc = idx & 7;                                     \
            cp16(wd + (m * GW_STR + kc * 4) * 4,                                \
                 &W[(size_t)(m0 + m) * K + (k0) + kc * 4]);                     \
        }                                                                       \
        _Pragma("unroll")                                                       \
        for (int c = 0; c < 4; c++) {                                           \
            int idx = t + c * 128;                                              \
            int kk = idx >> 4, n4 = (idx & 15) * 4;                             \
            cp16(xd + (kk * GX_STR + n4) * 4,                                   \
                 &Xb[(size_t)((k0) + kk) * NPIX + n0 + n4]);                    \
        }                                                                       \
        cp_commit();                                                            \
    } while (0)

    STAGE_G(0, 0);
    const int nchunks = K / 32;
    for (int c0 = 0; c0 < nchunks; c0++) {
        cp_wait0();
        __syncthreads();
        if (c0 < nchunks - 1) STAGE_G((c0 + 1) * 32, (c0 + 1) & 1);

        const float* Wt = gsm + ((c0 & 1) ? OFF_W1 : OFF_W0);
        const float* Xs = gsm + ((c0 & 1) ? OFF_X1 : OFF_X0);
#pragma unroll
        for (int ks = 0; ks < 4; ks++) {
            u32 a[2][4];
#pragma unroll
            for (int g = 0; g < 2; g++) {
                int mr = 64 * g + 16 * w + r;
                a[g][0] = cvt_tf32(Wt[(mr    ) * GW_STR + ks * 8 + cq    ]);
                a[g][1] = cvt_tf32(Wt[(mr + 8) * GW_STR + ks * 8 + cq    ]);
                a[g][2] = cvt_tf32(Wt[(mr    ) * GW_STR + ks * 8 + cq + 4]);
                a[g][3] = cvt_tf32(Wt[(mr + 8) * GW_STR + ks * 8 + cq + 4]);
            }
#pragma unroll
            for (int nt = 0; nt < 8; nt++) {
                u32 b[2];
                b[0] = cvt_tf32(Xs[(ks * 8 + cq    ) * GX_STR + nt * 8 + r]);
                b[1] = cvt_tf32(Xs[(ks * 8 + cq + 4) * GX_STR + nt * 8 + r]);
                mma_tf32(acc[0][nt], a[0], b);
                mma_tf32(acc[1][nt], a[1], b);
            }
        }
    }

#pragma unroll
    for (int g = 0; g < 2; g++) {
        int row0 = m0 + 64 * g + 16 * w + r;
        int row1 = row0 + 8;
        float sc0 = gg[row0] * rsqrtf(vv[row0] + EPSBN);
        float bi0 = bb[row0] - mm[row0] * sc0;
        float sc1 = gg[row1] * rsqrtf(vv[row1] + EPSBN);
        float bi1 = bb[row1] - mm[row1] * sc1;
#pragma unroll
        for (int nt = 0; nt < 8; nt++) {
            int col = n0 + nt * 8 + 2 * cq;
            *(float2*)&Ob[(size_t)row0 * NPIX + col] =
                make_float2(acc[g][nt][0] * sc0 + bi0, acc[g][nt][1] * sc0 + bi0);
            *(float2*)&Ob[(size_t)row1 * NPIX + col] =
                make_float2(acc[g][nt][2] * sc1 + bi1, acc[g][nt][3] * sc1 + bi1);
        }
    }
}

// ---------------------------------------------------------------------------
// Convert Q,K to half with transpose: g_qkv [ch][n] -> [n][d] per (b,h).
// Q gets QSCALE baked in. Grid (NPIX/128, BATCH*HEADS, 2), 128 threads.
// ---------------------------------------------------------------------------
__global__ __launch_bounds__(128) void qk_cvt_kernel()
{
    const float QSCALE = 0.17677669529663687f * 1.4426950408889634f;
    __shared__ float ts[32][132];
    const int n0 = blockIdx.x * 128;
    const int bh = blockIdx.y;
    const int b  = bh >> 2;
    const int h  = bh & 3;
    const int qk = blockIdx.z;
    const int t  = threadIdx.x;

    const float* src = g_qkv + ((size_t)(b * HIDDEN + h * 128 + (qk ? 32 : 0))) * NPIX + n0;
    __half* dst = (qk ? g_k16 : g_q16) + ((size_t)bh * NPIX + n0) * KEY_DIM;
    const float scale = qk ? 1.0f : QSCALE;

#pragma unroll
    for (int d = 0; d < 32; d++) ts[d][t] = src[(size_t)d * NPIX + t];
    __syncthreads();

    u32 out[16];
#pragma unroll
    for (int d = 0; d < 16; d++)
        out[d] = h2pack(ts[2 * d][t] * scale, ts[2 * d + 1][t] * scale);
#pragma unroll
    for (int q4 = 0; q4 < 4; q4++)
        *(uint4*)&dst[(size_t)t * 32 + q4 * 8] =
            make_uint4(out[q4 * 4], out[q4 * 4 + 1], out[q4 * 4 + 2], out[q4 * 4 + 3]);
}

// ---------------------------------------------------------------------------
// Convert V to half, same layout [bh][dv][n]. 512K threads x 4 elems.
// ---------------------------------------------------------------------------
__global__ __launch_bounds__(256) void v_cvt_kernel()
{
    int idx = blockIdx.x * 256 + threadIdx.x;        // < 2*4*64*1024
    if (idx >= BATCH * HEADS * HEAD_DIM * (NPIX / 4)) return;
    int n4   = (idx & 1023) * 4;
    int dv   = (idx >> 10) & 63;
    int bh   = idx >> 16;
    int b    = bh >> 2;
    int h    = bh & 3;
    const float* src = g_qkv + ((size_t)(b * HIDDEN + h * 128 + 64 + dv)) * NPIX + n4;
    __half* dst = g_v16 + ((size_t)bh * HEAD_DIM + dv) * NPIX + n4;
    float4 v = *(const float4*)src;
    *(uint2*)dst = make_uint2(h2pack(v.x, v.y), h2pack(v.z, v.w));
}

// ---------------------------------------------------------------------------
// Flash attention, fp16 m16n8k16 mma, fp32 accumulate.
// 128 threads (4 warps); warp owns 32 queries (two 16-row tiles).
// No P smem: PV A-fragments come directly from S C-fragments.
// Grid = (NPIX/128, BATCH*HEADS).
// ---------------------------------------------------------------------------
#define RK 40      // halves per Ks row (row = key j, 32 d + pad)
#define RV 72      // halves per Vs row (row = dv, 64 j + pad)
#define KS_H (64 * RK)   // 2560 halves
#define VS_H (64 * RV)   // 4608 halves
#define AKS0 0
#define AKS1 KS_H
#define AVS0 (2 * KS_H)
#define AVS1 (2 * KS_H + VS_H)

__global__ __launch_bounds__(128) void attn_mma_kernel()
{
    __shared__ __align__(16) __half smh[2 * KS_H + 2 * VS_H];  // 28672 B
    const int bh = blockIdx.y;
    const int i0   = blockIdx.x * 128;
    const int t    = threadIdx.x;
    const int w    = t >> 5;
    const int lane = t & 31;
    const int r    = lane >> 2;
    const int cq   = lane & 3;

    const __half* qb = g_q16 + (size_t)bh * NPIX * KEY_DIM;
    const __half* kb = g_k16 + (size_t)bh * NPIX * KEY_DIM;
    const __half* vb = g_v16 + (size_t)bh * HEAD_DIM * NPIX;
    const u32 smb = (u32)__cvta_generic_to_shared(smh);

    // Q fragments for 2 row-tiles, 2 k16-steps (d=0..15, 16..31)
    u32 qa[2][2][4];
#pragma unroll
    for (int rt = 0; rt < 2; rt++) {
        int row0 = i0 + 32 * w + 16 * rt + r;
#pragma unroll
        for (int ks = 0; ks < 2; ks++) {
            qa[rt][ks][0] = *(const u32*)&qb[(size_t)row0 * 32       + 16 * ks + 2 * cq];
            qa[rt][ks][1] = *(const u32*)&qb[(size_t)(row0 + 8) * 32 + 16 * ks + 2 * cq];
            qa[rt][ks][2] = *(const u32*)&qb[(size_t)row0 * 32       + 16 * ks + 8 + 2 * cq];
            qa[rt][ks][3] = *(const u32*)&qb[(size_t)(row0 + 8) * 32 + 16 * ks + 8 + 2 * cq];
        }
    }

    float o[2][8][4];
#pragma unroll
    for (int rt = 0; rt < 2; rt++)
#pragma unroll
        for (int nt = 0; nt < 8; nt++)
#pragma unroll
            for (int k = 0; k < 4; k++) o[rt][nt][k] = 0.f;
    float mx[2][2] = {{-1e30f, -1e30f}, {-1e30f, -1e30f}};
    float ll[2][2] = {{0.f, 0.f}, {0.f, 0.f}};

    // K tile: 64 rows x 32 halves = 256 cp16 (2/thread)
    // V tile: 64 rows x 64 halves = 512 cp16 (4/thread)
#define STAGE_A(kbase_idx, buf)                                                  \
    do {                                                                         \
        u32 kd = smb + ((buf) ? AKS1 : AKS0) * 2;                                \
        u32 vd = smb + ((buf) ? AVS1 : AVS0) * 2;                                \
        _Pragma("unroll")                                                        \
        for (int c = 0; c < 2; c++) {                                            \
            int idx = t + c * 128;                                               \
            int j = idx >> 2, seg = idx & 3;                                     \
            cp16(kd + (j * RK + seg * 8) * 2,                                    \
                 &kb[(size_t)((kbase_idx) + j) * 32 + seg * 8]);                 \
        }                                                                        \
        _Pragma("unroll")                                                        \
        for (int c = 0; c < 4; c++) {                                            \
            int idx = t + c * 128;                                               \
            int dv = idx >> 3, seg = idx & 7;                                    \
            cp16(vd + (dv * RV + seg * 8) * 2,                                   \
                 &vb[(size_t)dv * NPIX + (kbase_idx) + seg * 8]);                \
        }                                                                        \
        cp_commit();                                                             \
    } while (0)

    STAGE_A(0, 0);

    for (int tt = 0; tt < 64; tt++) {
        cp_wait0();
        __syncthreads();
        if (tt < 63) STAGE_A((tt + 1) * 64, (tt + 1) & 1);

        const __half* Ks = smh + ((tt & 1) ? AKS1 : AKS0);
        const __half* Vs = smh + ((tt & 1) ? AVS1 : AVS0);

        // ---- S = Q * K^T (both row-tiles share K B-fragments) ----
        float s[2][8][4];
#pragma unroll
        for (int rt = 0; rt < 2; rt++)
#pragma unroll
            for (int nt = 0; nt < 8; nt++)
#pragma unroll
                for (int k = 0; k < 4; k++) s[rt][nt][k] = 0.f;
#pragma unroll
        for (int ks = 0; ks < 2; ks++) {
#pragma unroll
            for (int nt = 0; nt < 8; nt++) {
                u32 b0 = *(const u32*)&Ks[(nt * 8 + r) * RK + 16 * ks + 2 * cq];
                u32 b1 = *(const u32*)&Ks[(nt * 8 + r) * RK + 16 * ks + 8 + 2 * cq];
                mma_f16(s[0][nt], qa[0][ks], b0, b1);
                mma_f16(s[1][nt], qa[1][ks], b0, b1);
            }
        }

        // ---- online softmax per row-tile ----
#pragma unroll
        for (int rt = 0; rt < 2; rt++) {
            float mx0 = mx[rt][0], mx1 = mx[rt][1];
#pragma unroll
            for (int nt = 0; nt < 8; nt++) {
                mx0 = fmaxf(mx0, fmaxf(s[rt][nt][0], s[rt][nt][1]));
                mx1 = fmaxf(mx1, fmaxf(s[rt][nt][2], s[rt][nt][3]));
            }
            mx0 = fmaxf(mx0, __shfl_xor_sync(0xffffffffu, mx0, 1));
            mx0 = fmaxf(mx0, __shfl_xor_sync(0xffffffffu, mx0, 2));
            mx1 = fmaxf(mx1, __shfl_xor_sync(0xffffffffu, mx1, 1));
            mx1 = fmaxf(mx1, __shfl_xor_sync(0xffffffffu, mx1, 2));
            float corr0 = ex2(mx[rt][0] - mx0);
            float corr1 = ex2(mx[rt][1] - mx1);
            mx[rt][0] = mx0; mx[rt][1] = mx1;

            float ps0 = 0.f, ps1 = 0.f;
#pragma unroll
            for (int nt = 0; nt < 8; nt++) {
                s[rt][nt][0] = ex2(s[rt][nt][0] - mx0);
                s[rt][nt][1] = ex2(s[rt][nt][1] - mx0);
                s[rt][nt][2] = ex2(s[rt][nt][2] - mx1);
                s[rt][nt][3] = ex2(s[rt][nt][3] - mx1);
                ps0 += s[rt][nt][0] + s[rt][nt][1];
                ps1 += s[rt][nt][2] + s[rt][nt][3];
            }
            ps0 += __shfl_xor_sync(0xffffffffu, ps0, 1);
            ps0 += __shfl_xor_sync(0xffffffffu, ps0, 2);
            ps1 += __shfl_xor_sync(0xffffffffu, ps1, 1);
            ps1 += __shfl_xor_sync(0xffffffffu, ps1, 2);
            ll[rt][0] = ll[rt][0] * corr0 + ps0;
            ll[rt][1] = ll[rt][1] * corr1 + ps1;

#pragma unroll
            for (int nt = 0; nt < 8; nt++) {
                o[rt][nt][0] *= corr0; o[rt][nt][1] *= corr0;
                o[rt][nt][2] *= corr1; o[rt][nt][3] *= corr1;
            }
        }

        // ---- O += P * V : A-fragments straight from S C-fragments ----
#pragma unroll
        for (int ks2 = 0; ks2 < 4; ks2++) {
            u32 pa[2][4];
#pragma unroll
            for (int rt = 0; rt < 2; rt++) {
                pa[rt][0] = h2pack(s[rt][2 * ks2    ][0], s[rt][2 * ks2    ][1]);
                pa[rt][1] = h2pack(s[rt][2 * ks2    ][2], s[rt][2 * ks2    ][3]);
                pa[rt][2] = h2pack(s[rt][2 * ks2 + 1][0], s[rt][2 * ks2 + 1][1]);
                pa[rt][3] = h2pack(s[rt][2 * ks2 + 1][2], s[rt][2 * ks2 + 1][3]);
            }
#pragma unroll
            for (int nt = 0; nt < 8; nt++) {
                u32 b0 = *(const u32*)&Vs[(nt * 8 + r) * RV + 16 * ks2 + 2 * cq];
                u32 b1 = *(const u32*)&Vs[(nt * 8 + r) * RV + 16 * ks2 + 8 + 2 * cq];
                mma_f16(o[0][nt], pa[0], b0, b1);
                mma_f16(o[1][nt], pa[1], b0, b1);
            }
        }
    }

    // ---- epilogue: normalize, store g_y [dv][n] ----
    const int b  = bh >> 2;
    const int h  = bh & 3;
    float* ybase = g_y + ((size_t)b * DIMC + h * 64) * NPIX;
#pragma unroll
    for (int rt = 0; rt < 2; rt++) {
        float inv0 = 1.f / ll[rt][0];
        float inv1 = 1.f / ll[rt][1];
        int row0 = i0 + 32 * w + 16 * rt + r;
        int row1 = row0 + 8;
#pragma unroll
        for (int nt = 0; nt < 8; nt++) {
            int dv0 = nt * 8 + 2 * cq;
            ybase[(size_t)(dv0    ) * NPIX + row0] = o[rt][nt][0] * inv0;
            ybase[(size_t)(dv0 + 1) * NPIX + row0] = o[rt][nt][1] * inv0;
            ybase[(size_t)(dv0    ) * NPIX + row1] = o[rt][nt][2] * inv1;
            ybase[(size_t)(dv0 + 1) * NPIX + row1] = o[rt][nt][3] * inv1;
        }
    }
}

// ---------------------------------------------------------------------------
// Depthwise 3x3 conv + BN, added into g_y. 4-wide strips, float4 y update.
// ---------------------------------------------------------------------------
__global__ __launch_bounds__(256) void pe_add_kernel(
    const float* __restrict__ pw, const float* __restrict__ pg,
    const float* __restrict__ pb, const float* __restrict__ pm,
    const float* __restrict__ pv)
{
    int idx = blockIdx.x * 256 + threadIdx.x;
    if (idx >= BATCH * DIMC * (NPIX / 4)) return;
    int n4 = (idx & 1023) * 4;
    int c  = (idx >> 10) & 255;
    int b  = idx >> 18;
    int yy = n4 >> 6, xx = n4 & 63;

    int vrow = (c >> 6) * 128 + 64 + (c & 63);
    const float* vimg = g_qkv + ((size_t)b * HIDDEN + vrow) * NPIX;

    float a0 = 0.f, a1 = 0.f, a2 = 0.f, a3 = 0.f;
#pragma unroll
    for (int ky = 0; ky < 3; ky++) {
        int y2 = yy + ky - 1;
        if (y2 < 0 || y2 >= HWDIM) continue;
        const float* row = vimg + y2 * HWDIM;
        float lm1 = (xx > 0)  ? row[xx - 1] : 0.f;
        float4 lc = *(const float4*)&row[xx];
        float l4  = (xx < 60) ? row[xx + 4] : 0.f;
        float w0 = pw[c * 9 + ky * 3 + 0];
        float w1 = pw[c * 9 + ky * 3 + 1];
        float w2 = pw[c * 9 + ky * 3 + 2];
        a0 += w0 * lm1  + w1 * lc.x + w2 * lc.y;
        a1 += w0 * lc.x + w1 * lc.y + w2 * lc.z;
        a2 += w0 * lc.y + w1 * lc.z + w2 * lc.w;
        a3 += w0 * lc.z + w1 * lc.w + w2 * l4;
    }
    float sc = pg[c] * rsqrtf(pv[c] + EPSBN);
    float bi = pb[c] - pm[c] * sc;
    float* yp = &g_y[((size_t)b * DIMC + c) * NPIX + n4];
    float4 y = *(float4*)yp;
    y.x += a0 * sc + bi;
    y.y += a1 * sc + bi;
    y.z += a2 * sc + bi;
    y.w += a3 * sc + bi;
    *(float4*)yp = y;
}

// ---------------------------------------------------------------------------
extern "C" void kernel_launch(void* const* d_in, const int* in_sizes, int n_in,
                              void* d_out, int out_size)
{
    const float* x      = (const float*)d_in[0];
    const float* qkv_w  = (const float*)d_in[1];
    const float* qkv_g  = (const float*)d_in[2];
    const float* qkv_b  = (const float*)d_in[3];
    const float* qkv_m  = (const float*)d_in[4];
    const float* qkv_v  = (const float*)d_in[5];
    const float* proj_w = (const float*)d_in[6];
    const float* proj_g = (const float*)d_in[7];
    const float* proj_b = (const float*)d_in[8];
    const float* proj_m = (const float*)d_in[9];
    const float* proj_v = (const float*)d_in[10];
    const float* pe_w   = (const float*)d_in[11];
    const float* pe_g   = (const float*)d_in[12];
    const float* pe_b   = (const float*)d_in[13];
    const float* pe_m   = (const float*)d_in[14];
    const float* pe_v   = (const float*)d_in[15];
    float* out = (float*)d_out;

    static float* qkv_buf = nullptr;
    static float* y_buf   = nullptr;
    if (!qkv_buf) {
        cudaGetSymbolAddress((void**)&qkv_buf, g_qkv);
        cudaGetSymbolAddress((void**)&y_buf,   g_y);
        cudaFuncSetAttribute(gemm_mma_kernel,
                             cudaFuncAttributeMaxDynamicSharedMemorySize,
                             GEMM_SMEM_BYTES);
    }

    // 1) QKV 1x1 conv + BN
    {
        dim3 grid(NPIX / 64, HIDDEN / 128, BATCH);
        gemm_mma_kernel<<<grid, 128, GEMM_SMEM_BYTES>>>(
            x, qkv_w, qkv_g, qkv_b, qkv_m, qkv_v, qkv_buf, HIDDEN, DIMC);
    }
    // 2) Convert Q/K (transpose) and V to half
    {
        dim3 gridqk(NPIX / 128, BATCH * HEADS, 2);
        qk_cvt_kernel<<<gridqk, 128>>>();
        int vtot = BATCH * HEADS * HEAD_DIM * (NPIX / 4);
        v_cvt_kernel<<<(vtot + 255) / 256, 256>>>();
    }
    // 3) Attention (fp16 mma)
    {
        dim3 grid(NPIX / 128, BATCH * HEADS);
        attn_mma_kernel<<<grid, 128>>>();
    }
    // 4) PE depthwise conv + BN, add into y
    {
        int total = BATCH * DIMC * (NPIX / 4);
        pe_add_kernel<<<(total + 255) / 256, 256>>>(pe_w, pe_g, pe_b, pe_m, pe_v);
    }
    // 5) proj 1x1 conv + BN -> out
    {
        dim3 grid(NPIX / 64, DIMC / 128, BATCH);
        gemm_mma_kernel<<<grid, 128, GEMM_SMEM_BYTES>>>(
            y_buf, proj_w, proj_g, proj_b, proj_m, proj_v, out, DIMC, DIMC);
    }
}